// round 3
// baseline (speedup 1.0000x reference)
#include <cuda_runtime.h>
#include <math.h>

#define BQ 16
#define CH 512
#define HH 56
#define WWD 56
#define NTOK 3136          // 56*56
#define NH 8
#define HD 64
#define AG 49
#define MROWS (BQ*NTOK)    // 50176

// ---------------- scratch (device globals; no allocations allowed) ----------
__device__ float g_q[(size_t)MROWS * CH];
__device__ float g_k[(size_t)MROWS * CH];
__device__ float g_v[(size_t)MROWS * CH];
__device__ float g_pre[(size_t)MROWS * CH];
__device__ float g_wqkv[3 * CH * CH];
__device__ float g_agent[BQ * AG * CH];
__device__ float g_bias1[NH * AG * NTOK];          // [h][a][n]
__device__ float g_bias2[(size_t)NH * NTOK * AG];  // [h][n][a]
__device__ float g_logits[(size_t)BQ * NH * AG * NTOK];
__device__ float g_agentv[BQ * NH * AG * HD];

// ---------------- weight packing: [q_w(512); kv_w(1024)] rows x 512 --------
__global__ void pack_w(const float* __restrict__ qw, const float* __restrict__ kvw) {
    int i = blockIdx.x * 256 + threadIdx.x;
    if (i < CH * CH) g_wqkv[i] = qw[i];
    else if (i < 3 * CH * CH) g_wqkv[i] = kvw[i - CH * CH];
}

// ---------------- bilinear 7->56 matching jax.image.resize ------------------
__device__ __forceinline__ float resize77(const float* __restrict__ img, int y, int x) {
    float sy = (y + 0.5f) * 0.125f - 0.5f;
    float sx = (x + 0.5f) * 0.125f - 0.5f;
    int y0 = (int)floorf(sy); float fy = sy - (float)y0;
    int x0 = (int)floorf(sx); float fx = sx - (float)x0;
    int y1 = y0 + 1, x1 = x0 + 1;
    float wy0 = 1.f - fy, wy1 = fy, wx0 = 1.f - fx, wx1 = fx;
    if (y0 < 0)  { y0 = 0; wy0 = 0.f; wy1 = 1.f; }        // edge weight renorm
    if (y1 > 6)  { y1 = 6; wy0 = 1.f; wy1 = 0.f; }
    if (x0 < 0)  { x0 = 0; wx0 = 0.f; wx1 = 1.f; }
    if (x1 > 6)  { x1 = 6; wx0 = 1.f; wx1 = 0.f; }
    return wy0 * (wx0 * img[y0 * 7 + x0] + wx1 * img[y0 * 7 + x1]) +
           wy1 * (wx0 * img[y1 * 7 + x0] + wx1 * img[y1 * 7 + x1]);
}

// bias1[h][a][n] = bilerp(an_bias[h,a]) + ah_bias[h,a,y] + aw_bias[h,a,x]
__global__ void make_bias1(const float* __restrict__ an, const float* __restrict__ ahb,
                           const float* __restrict__ awb) {
    int h = blockIdx.y, a = blockIdx.x;
    const float* img = an + (h * AG + a) * 49;
    for (int n = threadIdx.x; n < NTOK; n += blockDim.x) {
        int y = n / WWD, x = n % WWD;
        g_bias1[(h * AG + a) * NTOK + n] =
            resize77(img, y, x) + ahb[(h * AG + a) * HH + y] + awb[(h * AG + a) * WWD + x];
    }
}

// bias2[h][n][a] = bilerp(na_bias[h,a]) + ha_bias[h,y,a] + wa_bias[h,x,a]
__global__ void make_bias2(const float* __restrict__ na, const float* __restrict__ hab,
                           const float* __restrict__ wab) {
    int h = blockIdx.y, n = blockIdx.x;
    int y = n / WWD, x = n % WWD;
    int a = threadIdx.x;
    if (a < AG) {
        g_bias2[((size_t)h * NTOK + n) * AG + a] =
            resize77(na + (h * AG + a) * 49, y, x) + hab[(h * HH + y) * AG + a] + wab[(h * WWD + x) * AG + a];
    }
}

// ---------------- fp32 NT SGEMM: C[m,n] = sum_k A[m,k]*B[n,k] ---------------
// mode 0: A=Aext(x), B=g_wqkv, route columns to g_q/g_k/g_v.
// mode 1: A=g_pre, B=Bext(proj_w), out[m*512+n] = acc + bias[n].
// NOTE: device globals are resolved IN DEVICE CODE (host code cannot take
// the address of a __device__ symbol — that was the R1/R2 failure).
__global__ void __launch_bounds__(256) sgemm_nt(const float* __restrict__ Aext,
                                               const float* __restrict__ Bext,
                                               int K, int mode,
                                               const float* __restrict__ bias,
                                               float* __restrict__ out) {
    const float* A  = (mode == 0) ? Aext  : g_pre;
    const float* Bm = (mode == 0) ? g_wqkv : Bext;

    __shared__ float As[16][128];
    __shared__ float Bs[16][128];
    const int tid = threadIdx.x;
    const int m0 = blockIdx.y * 128;
    const int n0 = blockIdx.x * 128;
    const int lrow = tid >> 2;
    const int lcol = (tid & 3) << 2;
    const int tx = tid & 15;
    const int ty = tid >> 4;

    float acc[8][8];
#pragma unroll
    for (int i = 0; i < 8; i++)
#pragma unroll
        for (int j = 0; j < 8; j++) acc[i][j] = 0.f;

    const float* Ap = A + (size_t)(m0 + lrow) * K + lcol;
    const float* Bp = Bm + (size_t)(n0 + lrow) * K + lcol;

    for (int k0 = 0; k0 < K; k0 += 16) {
        float4 a0 = *(const float4*)(Ap + k0);
        float4 a1 = *(const float4*)(Ap + (size_t)64 * K + k0);
        float4 b0 = *(const float4*)(Bp + k0);
        float4 b1 = *(const float4*)(Bp + (size_t)64 * K + k0);
        __syncthreads();
        As[lcol + 0][lrow] = a0.x; As[lcol + 1][lrow] = a0.y;
        As[lcol + 2][lrow] = a0.z; As[lcol + 3][lrow] = a0.w;
        As[lcol + 0][lrow + 64] = a1.x; As[lcol + 1][lrow + 64] = a1.y;
        As[lcol + 2][lrow + 64] = a1.z; As[lcol + 3][lrow + 64] = a1.w;
        Bs[lcol + 0][lrow] = b0.x; Bs[lcol + 1][lrow] = b0.y;
        Bs[lcol + 2][lrow] = b0.z; Bs[lcol + 3][lrow] = b0.w;
        Bs[lcol + 0][lrow + 64] = b1.x; Bs[lcol + 1][lrow + 64] = b1.y;
        Bs[lcol + 2][lrow + 64] = b1.z; Bs[lcol + 3][lrow + 64] = b1.w;
        __syncthreads();
#pragma unroll
        for (int kk = 0; kk < 16; kk++) {
            float4 av0 = *(const float4*)&As[kk][ty * 8];
            float4 av1 = *(const float4*)&As[kk][ty * 8 + 4];
            float4 bv0 = *(const float4*)&Bs[kk][tx * 8];
            float4 bv1 = *(const float4*)&Bs[kk][tx * 8 + 4];
            float ar[8] = {av0.x, av0.y, av0.z, av0.w, av1.x, av1.y, av1.z, av1.w};
            float br[8] = {bv0.x, bv0.y, bv0.z, bv0.w, bv1.x, bv1.y, bv1.z, bv1.w};
#pragma unroll
            for (int i = 0; i < 8; i++)
#pragma unroll
                for (int j = 0; j < 8; j++) acc[i][j] = fmaf(ar[i], br[j], acc[i][j]);
        }
    }

    if (mode == 0) {
#pragma unroll
        for (int i = 0; i < 8; i++) {
            int m = m0 + ty * 8 + i;
#pragma unroll
            for (int j = 0; j < 8; j++) {
                int n = n0 + tx * 8 + j;
                float* dst = (n < CH) ? g_q : ((n < 2 * CH) ? g_k : g_v);
                dst[(size_t)m * CH + (n & (CH - 1))] = acc[i][j];
            }
        }
    } else {
#pragma unroll
        for (int i = 0; i < 8; i++) {
            int m = m0 + ty * 8 + i;
#pragma unroll
            for (int j = 0; j < 8; j++) {
                int n = n0 + tx * 8 + j;
                out[(size_t)m * CH + n] = acc[i][j] + bias[n];
            }
        }
    }
}

// ---------------- agent token pooling (7x7 grid of 8x8 means over q) --------
__global__ void agent_pool() {
    int a = blockIdx.x, b = blockIdx.y, c = threadIdx.x;
    int ph = a / 7, pw = a % 7;
    const float* base = g_q + (size_t)b * NTOK * CH;
    float s = 0.f;
#pragma unroll
    for (int ih = 0; ih < 8; ih++)
#pragma unroll
        for (int iw = 0; iw < 8; iw++)
            s += base[(size_t)((ph * 8 + ih) * WWD + pw * 8 + iw) * CH + c];
    g_agent[(b * AG + a) * CH + c] = s * (1.0f / 64.0f);
}

// ---------------- agent-side logits: (ah*scale) @ k^T + bias1 ---------------
__global__ void __launch_bounds__(256) agent_logits_kern() {
    __shared__ float ahs[AG][HD];
    __shared__ float ks[128][65];
    int b = blockIdx.z, h = blockIdx.y, n0 = blockIdx.x * 128;
    int tid = threadIdx.x;
    for (int t = tid; t < AG * HD; t += 256) {
        int a = t >> 6, d = t & 63;
        ahs[a][d] = g_agent[(b * AG + a) * CH + h * HD + d] * 0.125f;
    }
    for (int t = tid; t < 128 * 16; t += 256) {
        int j = t >> 4, d4 = (t & 15) << 2;
        int n = n0 + j;
        float4 kv = (n < NTOK) ? *(const float4*)&g_k[((size_t)b * NTOK + n) * CH + h * HD + d4]
                               : make_float4(0.f, 0.f, 0.f, 0.f);
        ks[j][d4] = kv.x; ks[j][d4 + 1] = kv.y; ks[j][d4 + 2] = kv.z; ks[j][d4 + 3] = kv.w;
    }
    __syncthreads();
    for (int t = tid; t < AG * 128; t += 256) {
        int a = t >> 7, j = t & 127;
        int n = n0 + j;
        if (n < NTOK) {
            float s = 0.f;
#pragma unroll
            for (int d = 0; d < HD; d++) s = fmaf(ahs[a][d], ks[j][d], s);
            g_logits[((size_t)(b * NH + h) * AG + a) * NTOK + n] = s + g_bias1[(h * AG + a) * NTOK + n];
        }
    }
}

// ---------------- softmax over n=3136 for each of B*NH*AG rows --------------
__global__ void softmax_rows() {
    int r = blockIdx.x;
    float* row = g_logits + (size_t)r * NTOK;
    __shared__ float red[128];
    int tid = threadIdx.x;
    float m = -1e30f;
    for (int i = tid; i < NTOK; i += 128) m = fmaxf(m, row[i]);
    red[tid] = m; __syncthreads();
    for (int s = 64; s > 0; s >>= 1) { if (tid < s) red[tid] = fmaxf(red[tid], red[tid + s]); __syncthreads(); }
    m = red[0]; __syncthreads();
    float sum = 0.f;
    for (int i = tid; i < NTOK; i += 128) { float e = __expf(row[i] - m); row[i] = e; sum += e; }
    red[tid] = sum; __syncthreads();
    for (int s = 64; s > 0; s >>= 1) { if (tid < s) red[tid] += red[tid + s]; __syncthreads(); }
    float inv = 1.0f / red[0];
    for (int i = tid; i < NTOK; i += 128) row[i] *= inv;
}

// ---------------- agent_v = attn @ v_h : per (b,h) 49x64 over K=3136 --------
__global__ void __launch_bounds__(256) agent_v_kern() {
    __shared__ float ps[AG][96];
    __shared__ float vs[96][HD];
    int bh = blockIdx.x;
    int b = bh >> 3, h = bh & 7;
    int tid = threadIdx.x;
    float acc[13];
#pragma unroll
    for (int i = 0; i < 13; i++) acc[i] = 0.f;
    const float* attn = g_logits + (size_t)bh * AG * NTOK;
    for (int n0 = 0; n0 < NTOK; n0 += 96) {
        __syncthreads();
        for (int t = tid; t < AG * 96; t += 256) {
            int a = t / 96, j = t % 96;
            int n = n0 + j;
            ps[a][j] = (n < NTOK) ? attn[a * NTOK + n] : 0.f;
        }
        for (int t = tid; t < 96 * 16; t += 256) {
            int j = t >> 4, d4 = (t & 15) << 2;
            int n = n0 + j;
            float4 vv = (n < NTOK) ? *(const float4*)&g_v[((size_t)b * NTOK + n) * CH + h * HD + d4]
                                   : make_float4(0.f, 0.f, 0.f, 0.f);
            vs[j][d4] = vv.x; vs[j][d4 + 1] = vv.y; vs[j][d4 + 2] = vv.z; vs[j][d4 + 3] = vv.w;
        }
        __syncthreads();
#pragma unroll
        for (int r = 0; r < 13; r++) {
            int idx = tid + 256 * r;
            if (idx < AG * HD) {
                int a = idx >> 6, d = idx & 63;
                float s = acc[r];
#pragma unroll
                for (int j = 0; j < 96; j++) s = fmaf(ps[a][j], vs[j][d], s);
                acc[r] = s;
            }
        }
    }
#pragma unroll
    for (int r = 0; r < 13; r++) {
        int idx = tid + 256 * r;
        if (idx < AG * HD) g_agentv[(size_t)bh * AG * HD + idx] = acc[r];
    }
}

// ---------------- q-side fused: logits(49) + softmax + @agent_v -------------
__global__ void __launch_bounds__(256) qside_kern() {
    __shared__ float ahs[AG][HD];
    __shared__ float avs[AG][HD];
    int b = blockIdx.z, h = blockIdx.y;
    int tid = threadIdx.x;
    int row = blockIdx.x * 256 + tid;
    for (int t = tid; t < AG * HD; t += 256) {
        int a = t >> 6, d = t & 63;
        ahs[a][d] = g_agent[(b * AG + a) * CH + h * HD + d] * 0.125f;
        avs[a][d] = g_agentv[((size_t)(b * NH + h) * AG + a) * HD + d];
    }
    __syncthreads();
    if (row >= NTOK) return;
    const float* qrow = g_q + ((size_t)b * NTOK + row) * CH + h * HD;
    const float* b2 = g_bias2 + ((size_t)h * NTOK + row) * AG;
    float lg[AG];
#pragma unroll
    for (int a = 0; a < AG; a++) lg[a] = b2[a];
#pragma unroll
    for (int dc = 0; dc < 4; dc++) {
        float qr[16];
#pragma unroll
        for (int i = 0; i < 16; i += 4) {
            float4 qv = *(const float4*)&qrow[dc * 16 + i];
            qr[i] = qv.x; qr[i + 1] = qv.y; qr[i + 2] = qv.z; qr[i + 3] = qv.w;
        }
#pragma unroll
        for (int a = 0; a < AG; a++) {
            float s = 0.f;
#pragma unroll
            for (int i = 0; i < 16; i++) s = fmaf(qr[i], ahs[a][dc * 16 + i], s);
            lg[a] += s;
        }
    }
    float m = -1e30f;
#pragma unroll
    for (int a = 0; a < AG; a++) m = fmaxf(m, lg[a]);
    float sum = 0.f;
#pragma unroll
    for (int a = 0; a < AG; a++) { lg[a] = __expf(lg[a] - m); sum += lg[a]; }
    float inv = 1.0f / sum;
    float* orow = g_pre + ((size_t)b * NTOK + row) * CH + h * HD;
#pragma unroll
    for (int dc = 0; dc < 4; dc++) {
        float o[16];
#pragma unroll
        for (int i = 0; i < 16; i++) o[i] = 0.f;
#pragma unroll
        for (int a = 0; a < AG; a++) {
            float p = lg[a];
#pragma unroll
            for (int i = 0; i < 16; i++) o[i] = fmaf(p, avs[a][dc * 16 + i], o[i]);
        }
#pragma unroll
        for (int i = 0; i < 16; i += 4) {
            float4 ov = make_float4(o[i] * inv, o[i + 1] * inv, o[i + 2] * inv, o[i + 3] * inv);
            *(float4*)&orow[dc * 16 + i] = ov;
        }
    }
}

// ---------------- depthwise 3x3 conv on v, accumulate into g_pre ------------
__global__ void dwc_kern(const float* __restrict__ w, const float* __restrict__ bias) {
    long long i = (long long)blockIdx.x * 256 + threadIdx.x;  // float4 index
    if (i >= (long long)MROWS * (CH / 4)) return;
    int c = (int)(i & (CH / 4 - 1)) << 2;
    long long rown = i >> 7;  // b*3136 + n
    int n = (int)(rown % NTOK);
    int b = (int)(rown / NTOK);
    int y = n / WWD, x = n % WWD;
    float a0 = bias[c], a1 = bias[c + 1], a2 = bias[c + 2], a3 = bias[c + 3];
#pragma unroll
    for (int ky = 0; ky < 3; ky++) {
        int yy = y + ky - 1;
        if (yy < 0 || yy >= HH) continue;
#pragma unroll
        for (int kx = 0; kx < 3; kx++) {
            int xx = x + kx - 1;
            if (xx < 0 || xx >= WWD) continue;
            float4 vv = *(const float4*)&g_v[((size_t)b * NTOK + yy * WWD + xx) * CH + c];
            int ki = ky * 3 + kx;
            a0 = fmaf(vv.x, w[(c + 0) * 9 + ki], a0);
            a1 = fmaf(vv.y, w[(c + 1) * 9 + ki], a1);
            a2 = fmaf(vv.z, w[(c + 2) * 9 + ki], a2);
            a3 = fmaf(vv.w, w[(c + 3) * 9 + ki], a3);
        }
    }
    float4* dst = (float4*)&g_pre[(size_t)rown * CH + c];
    float4 cur = *dst;
    cur.x += a0; cur.y += a1; cur.z += a2; cur.w += a3;
    *dst = cur;
}

// ---------------- launch --------------------------------------------------
extern "C" void kernel_launch(void* const* d_in, const int* in_sizes, int n_in,
                              void* d_out, int out_size) {
    // Input table may or may not include the scalar ints H, W (element count 1).
    // x is always d_in[0]. If d_in[1] is a scalar, weights start at 3, else at 1.
    int off = (in_sizes[1] == 1) ? 3 : 1;
    const float* x      = (const float*)d_in[0];
    const float* q_w    = (const float*)d_in[off + 0];
    const float* kv_w   = (const float*)d_in[off + 1];
    const float* proj_w = (const float*)d_in[off + 2];
    const float* proj_b = (const float*)d_in[off + 3];
    const float* dwc_w  = (const float*)d_in[off + 4];
    const float* dwc_b  = (const float*)d_in[off + 5];
    const float* an_b   = (const float*)d_in[off + 6];
    const float* na_b   = (const float*)d_in[off + 7];
    const float* ah_b   = (const float*)d_in[off + 8];
    const float* aw_b   = (const float*)d_in[off + 9];
    const float* ha_b   = (const float*)d_in[off + 10];
    const float* wa_b   = (const float*)d_in[off + 11];
    float* out = (float*)d_out;

    pack_w<<<(3 * CH * CH + 255) / 256, 256>>>(q_w, kv_w);
    make_bias1<<<dim3(AG, NH), 256>>>(an_b, ah_b, aw_b);
    make_bias2<<<dim3(NTOK, NH), 64>>>(na_b, ha_b, wa_b);

    // QKV GEMM: M=50176, N=1536, K=512  (B = g_wqkv resolved device-side)
    sgemm_nt<<<dim3(1536 / 128, MROWS / 128), 256>>>(x, nullptr, CH, 0, nullptr, nullptr);

    agent_pool<<<dim3(AG, BQ), CH>>>();
    agent_logits_kern<<<dim3((NTOK + 127) / 128, NH, BQ), 256>>>();
    softmax_rows<<<BQ * NH * AG, 128>>>();
    agent_v_kern<<<BQ * NH, 256>>>();
    qside_kern<<<dim3((NTOK + 255) / 256, NH, BQ), 256>>>();
    dwc_kern<<<(int)(((long long)MROWS * (CH / 4) + 255) / 256), 256>>>(dwc_w, dwc_b);

    // proj GEMM: M=50176, N=512, K=512, +bias -> d_out (A = g_pre device-side)
    sgemm_nt<<<dim3(CH / 128, MROWS / 128), 256>>>(nullptr, proj_w, CH, 1, proj_b, out);
}

// round 4
// speedup vs baseline: 1.7061x; 1.7061x over previous
#include <cuda_runtime.h>
#include <cuda_bf16.h>
#include <math.h>
#include <stdint.h>

#define BQ 16
#define CH 512
#define HH 56
#define WWD 56
#define NTOK 3136          // 56*56
#define NH 8
#define HD 64
#define AG 49
#define MROWS (BQ*NTOK)    // 50176
#define K3 1536            // tripled K for hi/lo split GEMM
#define KT 32              // k-tile (bf16 elements)
#define NKIT (K3/KT)       // 48
#define LDS_A (KT+8)       // padded smem row (40 bf16 = 80B; conflict-free ldmatrix)

// ---------------- scratch (device globals; no allocations allowed) ----------
__device__ float g_q[(size_t)MROWS * CH];
__device__ float g_k[(size_t)MROWS * CH];
__device__ float g_v[(size_t)MROWS * CH];
__device__ float g_pre[(size_t)MROWS * CH];
__device__ float g_agent[BQ * AG * CH];
__device__ float g_bias1[NH * AG * NTOK];          // [h][a][n]
__device__ float g_bias2[(size_t)NH * NTOK * AG];  // [h][n][a]
__device__ float g_logits[(size_t)BQ * NH * AG * NTOK];
__device__ float g_agentv[BQ * NH * AG * HD];
__device__ __nv_bfloat16 g_abf[(size_t)MROWS * K3];   // packed A (hi|hi|lo)
__device__ __nv_bfloat16 g_bbf[(size_t)K3 * K3];      // packed B (hi|lo|hi), up to 1536 rows

// ---------------- hi/lo split helpers ---------------------------------------
__device__ __forceinline__ void split2(float v, __nv_bfloat16& hi, __nv_bfloat16& lo) {
    hi = __float2bfloat16(v);
    lo = __float2bfloat16(v - __bfloat162float(hi));
}

// pack A: src [M][512] fp32 -> g_abf [M][1536] = [hi | hi | lo]
// use_pre: read from g_pre (device symbol must be resolved device-side)
__global__ void pack_a(const float* __restrict__ src_ext, int use_pre) {
    const float* src = use_pre ? g_pre : src_ext;
    long long i = (long long)blockIdx.x * 256 + threadIdx.x;   // one per 2 floats
    int row = (int)(i >> 8);
    int kp = ((int)i & 255) * 2;
    float2 v = *(const float2*)&src[(size_t)row * CH + kp];
    __nv_bfloat162 h2, l2;
    split2(v.x, h2.x, l2.x);
    split2(v.y, h2.y, l2.y);
    __nv_bfloat16* dst = g_abf + (size_t)row * K3;
    *(__nv_bfloat162*)&dst[kp]        = h2;
    *(__nv_bfloat162*)&dst[kp + 512]  = h2;
    *(__nv_bfloat162*)&dst[kp + 1024] = l2;
}

// pack B: rows n of weight matrix -> g_bbf [n][1536] = [hi | lo | hi]
// mode 0 (QKV): n<512 from q_w, else kv_w (1536 rows). mode 1: proj_w (512 rows).
__global__ void pack_b(const float* __restrict__ w0, const float* __restrict__ w1, int qkv) {
    long long i = (long long)blockIdx.x * 256 + threadIdx.x;
    int row = (int)(i >> 8);
    int kp = ((int)i & 255) * 2;
    const float* src;
    if (qkv) src = (row < CH) ? (w0 + (size_t)row * CH) : (w1 + (size_t)(row - CH) * CH);
    else     src = w0 + (size_t)row * CH;
    float2 v = *(const float2*)&src[kp];
    __nv_bfloat162 h2, l2;
    split2(v.x, h2.x, l2.x);
    split2(v.y, h2.y, l2.y);
    __nv_bfloat16* dst = g_bbf + (size_t)row * K3;
    *(__nv_bfloat162*)&dst[kp]        = h2;
    *(__nv_bfloat162*)&dst[kp + 512]  = l2;
    *(__nv_bfloat162*)&dst[kp + 1024] = h2;
}

// ---------------- bf16 tensor-core GEMM: C[m,n] = sum_k A[m,k]*B[n,k] -------
// 128x128 block tile, KT=32 k-tile, cp.async double buffer, mma.m16n8k16.
// mode 0: route columns (n of 1536) to g_q/g_k/g_v. mode 1: out += bias.
__device__ __forceinline__ void cp16(uint32_t sp, const void* gp) {
    asm volatile("cp.async.cg.shared.global [%0], [%1], 16;\n" :: "r"(sp), "l"(gp));
}
__device__ __forceinline__ void ldsm4(uint32_t& r0, uint32_t& r1, uint32_t& r2, uint32_t& r3, uint32_t addr) {
    asm volatile("ldmatrix.sync.aligned.m8n8.x4.shared.b16 {%0,%1,%2,%3}, [%4];"
                 : "=r"(r0), "=r"(r1), "=r"(r2), "=r"(r3) : "r"(addr));
}
__device__ __forceinline__ void mma16816(float* c, const uint32_t* a, uint32_t b0, uint32_t b1) {
    asm volatile("mma.sync.aligned.m16n8k16.row.col.f32.bf16.bf16.f32 "
                 "{%0,%1,%2,%3}, {%4,%5,%6,%7}, {%8,%9}, {%0,%1,%2,%3};"
                 : "+f"(c[0]), "+f"(c[1]), "+f"(c[2]), "+f"(c[3])
                 : "r"(a[0]), "r"(a[1]), "r"(a[2]), "r"(a[3]), "r"(b0), "r"(b1));
}

__global__ void __launch_bounds__(256) gemm_bf16(int mode, const float* __restrict__ bias,
                                                 float* __restrict__ out) {
    __shared__ __nv_bfloat16 As[2][128][LDS_A];
    __shared__ __nv_bfloat16 Bs[2][128][LDS_A];
    const int tid = threadIdx.x;
    const int lane = tid & 31;
    const int warp = tid >> 5;
    const int wm = (warp & 1) * 64;      // warp tile 64 x 32
    const int wn = (warp >> 1) * 32;
    const int m0 = blockIdx.y * 128;
    const int n0 = blockIdx.x * 128;

    float acc[4][4][4];
#pragma unroll
    for (int i = 0; i < 4; i++)
#pragma unroll
        for (int j = 0; j < 4; j++)
#pragma unroll
            for (int l = 0; l < 4; l++) acc[i][j][l] = 0.f;

    // cp.async tile loader: 512 chunks of 16B per operand, 2 per thread
    const int c0row = tid >> 2, c0k = (tid & 3) * 8;
    const int c1row = (tid + 256) >> 2, c1k = ((tid + 256) & 3) * 8;

    // ldmatrix addresses (per k-half selected later)
    const int a_row = wm + (lane & 15);
    const int a_koff = ((lane >> 4) << 3);
    const int b_rbase = wn + (lane & 7) + ((lane >> 4) << 3);
    const int b_koff = (((lane >> 3) & 1) << 3);

#define ISSUE(buf, kt)                                                                  \
    {                                                                                   \
        int k0 = (kt) * KT;                                                             \
        cp16(__cvta_generic_to_shared(&As[buf][c0row][c0k]),                            \
             g_abf + (size_t)(m0 + c0row) * K3 + k0 + c0k);                             \
        cp16(__cvta_generic_to_shared(&As[buf][c1row][c1k]),                            \
             g_abf + (size_t)(m0 + c1row) * K3 + k0 + c1k);                             \
        cp16(__cvta_generic_to_shared(&Bs[buf][c0row][c0k]),                            \
             g_bbf + (size_t)(n0 + c0row) * K3 + k0 + c0k);                             \
        cp16(__cvta_generic_to_shared(&Bs[buf][c1row][c1k]),                            \
             g_bbf + (size_t)(n0 + c1row) * K3 + k0 + c1k);                             \
        asm volatile("cp.async.commit_group;\n");                                       \
    }

    ISSUE(0, 0);
    int buf = 0;
    for (int kt = 0; kt < NKIT; kt++) {
        asm volatile("cp.async.wait_group 0;\n");
        __syncthreads();
        if (kt + 1 < NKIT) ISSUE(buf ^ 1, kt + 1);
#pragma unroll
        for (int ks = 0; ks < KT; ks += 16) {
            uint32_t af[4][4], bfr[2][4];
#pragma unroll
            for (int fm = 0; fm < 4; fm++) {
                uint32_t ad = __cvta_generic_to_shared(&As[buf][fm * 16 + a_row][ks + a_koff]);
                ldsm4(af[fm][0], af[fm][1], af[fm][2], af[fm][3], ad);
            }
#pragma unroll
            for (int fn = 0; fn < 2; fn++) {
                uint32_t bd = __cvta_generic_to_shared(&Bs[buf][fn * 16 + b_rbase][ks + b_koff]);
                ldsm4(bfr[fn][0], bfr[fn][1], bfr[fn][2], bfr[fn][3], bd);
            }
#pragma unroll
            for (int fm = 0; fm < 4; fm++)
#pragma unroll
                for (int nc = 0; nc < 4; nc++) {
                    uint32_t b0 = bfr[nc >> 1][(nc & 1) ? 2 : 0];
                    uint32_t b1 = bfr[nc >> 1][(nc & 1) ? 3 : 1];
                    mma16816(acc[fm][nc], af[fm], b0, b1);
                }
        }
        buf ^= 1;
    }

    // epilogue
    const int r0 = lane >> 2;
    const int cp = (lane & 3) * 2;
#pragma unroll
    for (int fm = 0; fm < 4; fm++) {
#pragma unroll
        for (int nc = 0; nc < 4; nc++) {
            int m = m0 + wm + fm * 16 + r0;
            int n = n0 + wn + nc * 8 + cp;
            if (mode == 0) {
                float* dst = (n < CH) ? g_q : ((n < 2 * CH) ? g_k : g_v);
                int nn = n & (CH - 1);
                *(float2*)&dst[(size_t)m * CH + nn] = make_float2(acc[fm][nc][0], acc[fm][nc][1]);
                *(float2*)&dst[(size_t)(m + 8) * CH + nn] = make_float2(acc[fm][nc][2], acc[fm][nc][3]);
            } else {
                float2 bb = *(const float2*)&bias[n];
                *(float2*)&out[(size_t)m * CH + n] =
                    make_float2(acc[fm][nc][0] + bb.x, acc[fm][nc][1] + bb.y);
                *(float2*)&out[(size_t)(m + 8) * CH + n] =
                    make_float2(acc[fm][nc][2] + bb.x, acc[fm][nc][3] + bb.y);
            }
        }
    }
#undef ISSUE
}

// ---------------- bilinear 7->56 matching jax.image.resize ------------------
__device__ __forceinline__ float resize77(const float* __restrict__ img, int y, int x) {
    float sy = (y + 0.5f) * 0.125f - 0.5f;
    float sx = (x + 0.5f) * 0.125f - 0.5f;
    int y0 = (int)floorf(sy); float fy = sy - (float)y0;
    int x0 = (int)floorf(sx); float fx = sx - (float)x0;
    int y1 = y0 + 1, x1 = x0 + 1;
    float wy0 = 1.f - fy, wy1 = fy, wx0 = 1.f - fx, wx1 = fx;
    if (y0 < 0)  { y0 = 0; wy0 = 0.f; wy1 = 1.f; }
    if (y1 > 6)  { y1 = 6; wy0 = 1.f; wy1 = 0.f; }
    if (x0 < 0)  { x0 = 0; wx0 = 0.f; wx1 = 1.f; }
    if (x1 > 6)  { x1 = 6; wx0 = 1.f; wx1 = 0.f; }
    return wy0 * (wx0 * img[y0 * 7 + x0] + wx1 * img[y0 * 7 + x1]) +
           wy1 * (wx0 * img[y1 * 7 + x0] + wx1 * img[y1 * 7 + x1]);
}

__global__ void make_bias1(const float* __restrict__ an, const float* __restrict__ ahb,
                           const float* __restrict__ awb) {
    int h = blockIdx.y, a = blockIdx.x;
    const float* img = an + (h * AG + a) * 49;
    for (int n = threadIdx.x; n < NTOK; n += blockDim.x) {
        int y = n / WWD, x = n % WWD;
        g_bias1[(h * AG + a) * NTOK + n] =
            resize77(img, y, x) + ahb[(h * AG + a) * HH + y] + awb[(h * AG + a) * WWD + x];
    }
}

__global__ void make_bias2(const float* __restrict__ na, const float* __restrict__ hab,
                           const float* __restrict__ wab) {
    int h = blockIdx.y, n = blockIdx.x;
    int y = n / WWD, x = n % WWD;
    int a = threadIdx.x;
    if (a < AG) {
        g_bias2[((size_t)h * NTOK + n) * AG + a] =
            resize77(na + (h * AG + a) * 49, y, x) + hab[(h * HH + y) * AG + a] + wab[(h * WWD + x) * AG + a];
    }
}

// ---------------- agent token pooling (7x7 grid of 8x8 means over q) --------
__global__ void agent_pool() {
    int a = blockIdx.x, b = blockIdx.y, c = threadIdx.x;
    int ph = a / 7, pw = a % 7;
    const float* base = g_q + (size_t)b * NTOK * CH;
    float s = 0.f;
#pragma unroll
    for (int ih = 0; ih < 8; ih++)
#pragma unroll
        for (int iw = 0; iw < 8; iw++)
            s += base[(size_t)((ph * 8 + ih) * WWD + pw * 8 + iw) * CH + c];
    g_agent[(b * AG + a) * CH + c] = s * (1.0f / 64.0f);
}

// ---------------- agent-side logits: (ah*scale) @ k^T + bias1 ---------------
__global__ void __launch_bounds__(256) agent_logits_kern() {
    __shared__ float ahs[AG][HD];
    __shared__ float ks[128][65];
    int b = blockIdx.z, h = blockIdx.y, n0 = blockIdx.x * 128;
    int tid = threadIdx.x;
    for (int t = tid; t < AG * HD; t += 256) {
        int a = t >> 6, d = t & 63;
        ahs[a][d] = g_agent[(b * AG + a) * CH + h * HD + d] * 0.125f;
    }
    for (int t = tid; t < 128 * 16; t += 256) {
        int j = t >> 4, d4 = (t & 15) << 2;
        int n = n0 + j;
        float4 kv = (n < NTOK) ? *(const float4*)&g_k[((size_t)b * NTOK + n) * CH + h * HD + d4]
                               : make_float4(0.f, 0.f, 0.f, 0.f);
        ks[j][d4] = kv.x; ks[j][d4 + 1] = kv.y; ks[j][d4 + 2] = kv.z; ks[j][d4 + 3] = kv.w;
    }
    __syncthreads();
    for (int t = tid; t < AG * 128; t += 256) {
        int a = t >> 7, j = t & 127;
        int n = n0 + j;
        if (n < NTOK) {
            float s = 0.f;
#pragma unroll
            for (int d = 0; d < HD; d++) s = fmaf(ahs[a][d], ks[j][d], s);
            g_logits[((size_t)(b * NH + h) * AG + a) * NTOK + n] = s + g_bias1[(h * AG + a) * NTOK + n];
        }
    }
}

// ---------------- softmax over n=3136 for each of B*NH*AG rows --------------
__global__ void softmax_rows() {
    int r = blockIdx.x;
    float* row = g_logits + (size_t)r * NTOK;
    __shared__ float red[128];
    int tid = threadIdx.x;
    float m = -1e30f;
    for (int i = tid; i < NTOK; i += 128) m = fmaxf(m, row[i]);
    red[tid] = m; __syncthreads();
    for (int s = 64; s > 0; s >>= 1) { if (tid < s) red[tid] = fmaxf(red[tid], red[tid + s]); __syncthreads(); }
    m = red[0]; __syncthreads();
    float sum = 0.f;
    for (int i = tid; i < NTOK; i += 128) { float e = __expf(row[i] - m); row[i] = e; sum += e; }
    red[tid] = sum; __syncthreads();
    for (int s = 64; s > 0; s >>= 1) { if (tid < s) red[tid] += red[tid + s]; __syncthreads(); }
    float inv = 1.0f / red[0];
    for (int i = tid; i < NTOK; i += 128) row[i] *= inv;
}

// ---------------- agent_v = attn @ v_h : per (b,h) 49x64 over K=3136 --------
__global__ void __launch_bounds__(256) agent_v_kern() {
    __shared__ float ps[AG][96];
    __shared__ float vs[96][HD];
    int bh = blockIdx.x;
    int b = bh >> 3, h = bh & 7;
    int tid = threadIdx.x;
    float acc[13];
#pragma unroll
    for (int i = 0; i < 13; i++) acc[i] = 0.f;
    const float* attn = g_logits + (size_t)bh * AG * NTOK;
    for (int n0 = 0; n0 < NTOK; n0 += 96) {
        __syncthreads();
        for (int t = tid; t < AG * 96; t += 256) {
            int a = t / 96, j = t % 96;
            int n = n0 + j;
            ps[a][j] = (n < NTOK) ? attn[a * NTOK + n] : 0.f;
        }
        for (int t = tid; t < 96 * 16; t += 256) {
            int j = t >> 4, d4 = (t & 15) << 2;
            int n = n0 + j;
            float4 vv = (n < NTOK) ? *(const float4*)&g_v[((size_t)b * NTOK + n) * CH + h * HD + d4]
                                   : make_float4(0.f, 0.f, 0.f, 0.f);
            vs[j][d4] = vv.x; vs[j][d4 + 1] = vv.y; vs[j][d4 + 2] = vv.z; vs[j][d4 + 3] = vv.w;
        }
        __syncthreads();
#pragma unroll
        for (int r = 0; r < 13; r++) {
            int idx = tid + 256 * r;
            if (idx < AG * HD) {
                int a = idx >> 6, d = idx & 63;
                float s = acc[r];
#pragma unroll
                for (int j = 0; j < 96; j++) s = fmaf(ps[a][j], vs[j][d], s);
                acc[r] = s;
            }
        }
    }
#pragma unroll
    for (int r = 0; r < 13; r++) {
        int idx = tid + 256 * r;
        if (idx < AG * HD) g_agentv[(size_t)bh * AG * HD + idx] = acc[r];
    }
}

// ---------------- q-side fused: logits(49) + softmax + @agent_v -------------
__global__ void __launch_bounds__(256) qside_kern() {
    __shared__ float ahs[AG][HD];
    __shared__ float avs[AG][HD];
    int b = blockIdx.z, h = blockIdx.y;
    int tid = threadIdx.x;
    int row = blockIdx.x * 256 + tid;
    for (int t = tid; t < AG * HD; t += 256) {
        int a = t >> 6, d = t & 63;
        ahs[a][d] = g_agent[(b * AG + a) * CH + h * HD + d] * 0.125f;
        avs[a][d] = g_agentv[((size_t)(b * NH + h) * AG + a) * HD + d];
    }
    __syncthreads();
    if (row >= NTOK) return;
    const float* qrow = g_q + ((size_t)b * NTOK + row) * CH + h * HD;
    const float* b2 = g_bias2 + ((size_t)h * NTOK + row) * AG;
    float lg[AG];
#pragma unroll
    for (int a = 0; a < AG; a++) lg[a] = b2[a];
#pragma unroll
    for (int dc = 0; dc < 4; dc++) {
        float qr[16];
#pragma unroll
        for (int i = 0; i < 16; i += 4) {
            float4 qv = *(const float4*)&qrow[dc * 16 + i];
            qr[i] = qv.x; qr[i + 1] = qv.y; qr[i + 2] = qv.z; qr[i + 3] = qv.w;
        }
#pragma unroll
        for (int a = 0; a < AG; a++) {
            float s = 0.f;
#pragma unroll
            for (int i = 0; i < 16; i++) s = fmaf(qr[i], ahs[a][dc * 16 + i], s);
            lg[a] += s;
        }
    }
    float m = -1e30f;
#pragma unroll
    for (int a = 0; a < AG; a++) m = fmaxf(m, lg[a]);
    float sum = 0.f;
#pragma unroll
    for (int a = 0; a < AG; a++) { lg[a] = __expf(lg[a] - m); sum += lg[a]; }
    float inv = 1.0f / sum;
    float* orow = g_pre + ((size_t)b * NTOK + row) * CH + h * HD;
#pragma unroll
    for (int dc = 0; dc < 4; dc++) {
        float o[16];
#pragma unroll
        for (int i = 0; i < 16; i++) o[i] = 0.f;
#pragma unroll
        for (int a = 0; a < AG; a++) {
            float p = lg[a];
#pragma unroll
            for (int i = 0; i < 16; i++) o[i] = fmaf(p, avs[a][dc * 16 + i], o[i]);
        }
#pragma unroll
        for (int i = 0; i < 16; i += 4) {
            float4 ov = make_float4(o[i] * inv, o[i + 1] * inv, o[i + 2] * inv, o[i + 3] * inv);
            *(float4*)&orow[dc * 16 + i] = ov;
        }
    }
}

// ---------------- depthwise 3x3 conv on v, accumulate into g_pre ------------
__global__ void dwc_kern(const float* __restrict__ w, const float* __restrict__ bias) {
    long long i = (long long)blockIdx.x * 256 + threadIdx.x;  // float4 index
    if (i >= (long long)MROWS * (CH / 4)) return;
    int c = (int)(i & (CH / 4 - 1)) << 2;
    long long rown = i >> 7;  // b*3136 + n
    int n = (int)(rown % NTOK);
    int b = (int)(rown / NTOK);
    int y = n / WWD, x = n % WWD;
    float a0 = bias[c], a1 = bias[c + 1], a2 = bias[c + 2], a3 = bias[c + 3];
#pragma unroll
    for (int ky = 0; ky < 3; ky++) {
        int yy = y + ky - 1;
        if (yy < 0 || yy >= HH) continue;
#pragma unroll
        for (int kx = 0; kx < 3; kx++) {
            int xx = x + kx - 1;
            if (xx < 0 || xx >= WWD) continue;
            float4 vv = *(const float4*)&g_v[((size_t)b * NTOK + yy * WWD + xx) * CH + c];
            int ki = ky * 3 + kx;
            a0 = fmaf(vv.x, w[(c + 0) * 9 + ki], a0);
            a1 = fmaf(vv.y, w[(c + 1) * 9 + ki], a1);
            a2 = fmaf(vv.z, w[(c + 2) * 9 + ki], a2);
            a3 = fmaf(vv.w, w[(c + 3) * 9 + ki], a3);
        }
    }
    float4* dst = (float4*)&g_pre[(size_t)rown * CH + c];
    float4 cur = *dst;
    cur.x += a0; cur.y += a1; cur.z += a2; cur.w += a3;
    *dst = cur;
}

// ---------------- launch --------------------------------------------------
extern "C" void kernel_launch(void* const* d_in, const int* in_sizes, int n_in,
                              void* d_out, int out_size) {
    int off = (in_sizes[1] == 1) ? 3 : 1;
    const float* x      = (const float*)d_in[0];
    const float* q_w    = (const float*)d_in[off + 0];
    const float* kv_w   = (const float*)d_in[off + 1];
    const float* proj_w = (const float*)d_in[off + 2];
    const float* proj_b = (const float*)d_in[off + 3];
    const float* dwc_w  = (const float*)d_in[off + 4];
    const float* dwc_b  = (const float*)d_in[off + 5];
    const float* an_b   = (const float*)d_in[off + 6];
    const float* na_b   = (const float*)d_in[off + 7];
    const float* ah_b   = (const float*)d_in[off + 8];
    const float* aw_b   = (const float*)d_in[off + 9];
    const float* ha_b   = (const float*)d_in[off + 10];
    const float* wa_b   = (const float*)d_in[off + 11];
    float* out = (float*)d_out;

    make_bias1<<<dim3(AG, NH), 256>>>(an_b, ah_b, aw_b);
    make_bias2<<<dim3(NTOK, NH), 64>>>(na_b, ha_b, wa_b);

    // pack + QKV GEMM (M=50176, N=1536, K3=1536 split)
    pack_a<<<MROWS, 256>>>(x, 0);
    pack_b<<<3 * CH, 256>>>(q_w, kv_w, 1);
    gemm_bf16<<<dim3(1536 / 128, MROWS / 128), 256>>>(0, nullptr, nullptr);

    agent_pool<<<dim3(AG, BQ), CH>>>();
    agent_logits_kern<<<dim3((NTOK + 127) / 128, NH, BQ), 256>>>();
    softmax_rows<<<BQ * NH * AG, 128>>>();
    agent_v_kern<<<BQ * NH, 256>>>();
    qside_kern<<<dim3((NTOK + 255) / 256, NH, BQ), 256>>>();
    dwc_kern<<<(int)(((long long)MROWS * (CH / 4) + 255) / 256), 256>>>(dwc_w, dwc_b);

    // pack + proj GEMM (M=50176, N=512, K3=1536 split) -> d_out (+bias)
    pack_a<<<MROWS, 256>>>(nullptr, 1);
    pack_b<<<CH, 256>>>(proj_w, nullptr, 0);
    gemm_bf16<<<dim3(CH / 128, MROWS / 128), 256>>>(1, proj_b, out);
}

// round 5
// speedup vs baseline: 1.9497x; 1.1428x over previous
#include <cuda_runtime.h>
#include <cuda_bf16.h>
#include <math.h>
#include <stdint.h>

#define BQ 16
#define CH 512
#define HH 56
#define WWD 56
#define NTOK 3136          // 56*56
#define NH 8
#define HD 64
#define AG 49
#define MROWS (BQ*NTOK)    // 50176
#define K3 1536            // tripled K for hi/lo split GEMM
#define KT 32              // k-tile (bf16 elements)
#define NKIT (K3/KT)       // 48
#define LDS_A (KT+8)

// ---------------- scratch ----------------------------------------------------
__device__ float g_q[(size_t)MROWS * CH];
__device__ float g_k[(size_t)MROWS * CH];
__device__ float g_v[(size_t)MROWS * CH];
__device__ float g_pre[(size_t)MROWS * CH];
__device__ float g_agent[BQ * AG * CH];
__device__ float g_bias1[NH * AG * NTOK];          // [h][a][n]
__device__ float g_bias2[(size_t)NH * NTOK * AG];  // [h][n][a]
__device__ float g_logits[(size_t)BQ * NH * AG * NTOK];
__device__ float g_agentv[BQ * NH * AG * HD];
__device__ __nv_bfloat16 g_abf[(size_t)MROWS * K3];
__device__ __nv_bfloat16 g_bbf[(size_t)K3 * K3];

// ---------------- helpers ----------------------------------------------------
__device__ __forceinline__ void split2(float v, __nv_bfloat16& hi, __nv_bfloat16& lo) {
    hi = __float2bfloat16(v);
    lo = __float2bfloat16(v - __bfloat162float(hi));
}
__device__ __forceinline__ uint32_t pack_bf2(__nv_bfloat16 a, __nv_bfloat16 b) {
    return ((uint32_t)__bfloat16_as_ushort(b) << 16) | (uint32_t)__bfloat16_as_ushort(a);
}
__device__ __forceinline__ uint32_t smem_u32(const void* p) {
    return (uint32_t)__cvta_generic_to_shared(p);
}
__device__ __forceinline__ void ldsm4(uint32_t& r0, uint32_t& r1, uint32_t& r2, uint32_t& r3, uint32_t addr) {
    asm volatile("ldmatrix.sync.aligned.m8n8.x4.shared.b16 {%0,%1,%2,%3}, [%4];"
                 : "=r"(r0), "=r"(r1), "=r"(r2), "=r"(r3) : "r"(addr));
}
__device__ __forceinline__ void ldsm4t(uint32_t& r0, uint32_t& r1, uint32_t& r2, uint32_t& r3, uint32_t addr) {
    asm volatile("ldmatrix.sync.aligned.m8n8.x4.trans.shared.b16 {%0,%1,%2,%3}, [%4];"
                 : "=r"(r0), "=r"(r1), "=r"(r2), "=r"(r3) : "r"(addr));
}
__device__ __forceinline__ void mma16816(float* c, const uint32_t* a, uint32_t b0, uint32_t b1) {
    asm volatile("mma.sync.aligned.m16n8k16.row.col.f32.bf16.bf16.f32 "
                 "{%0,%1,%2,%3}, {%4,%5,%6,%7}, {%8,%9}, {%0,%1,%2,%3};"
                 : "+f"(c[0]), "+f"(c[1]), "+f"(c[2]), "+f"(c[3])
                 : "r"(a[0]), "r"(a[1]), "r"(a[2]), "r"(a[3]), "r"(b0), "r"(b1));
}
__device__ __forceinline__ void cp16(uint32_t sp, const void* gp) {
    asm volatile("cp.async.cg.shared.global [%0], [%1], 16;\n" :: "r"(sp), "l"(gp));
}

// ---------------- pack kernels for big GEMMs ---------------------------------
__global__ void pack_a(const float* __restrict__ src_ext, int use_pre) {
    const float* src = use_pre ? g_pre : src_ext;
    long long i = (long long)blockIdx.x * 256 + threadIdx.x;
    int row = (int)(i >> 8);
    int kp = ((int)i & 255) * 2;
    float2 v = *(const float2*)&src[(size_t)row * CH + kp];
    __nv_bfloat162 h2, l2;
    split2(v.x, h2.x, l2.x);
    split2(v.y, h2.y, l2.y);
    __nv_bfloat16* dst = g_abf + (size_t)row * K3;
    *(__nv_bfloat162*)&dst[kp]        = h2;
    *(__nv_bfloat162*)&dst[kp + 512]  = h2;
    *(__nv_bfloat162*)&dst[kp + 1024] = l2;
}
__global__ void pack_b(const float* __restrict__ w0, const float* __restrict__ w1, int qkv) {
    long long i = (long long)blockIdx.x * 256 + threadIdx.x;
    int row = (int)(i >> 8);
    int kp = ((int)i & 255) * 2;
    const float* src;
    if (qkv) src = (row < CH) ? (w0 + (size_t)row * CH) : (w1 + (size_t)(row - CH) * CH);
    else     src = w0 + (size_t)row * CH;
    float2 v = *(const float2*)&src[kp];
    __nv_bfloat162 h2, l2;
    split2(v.x, h2.x, l2.x);
    split2(v.y, h2.y, l2.y);
    __nv_bfloat16* dst = g_bbf + (size_t)row * K3;
    *(__nv_bfloat162*)&dst[kp]        = h2;
    *(__nv_bfloat162*)&dst[kp + 512]  = l2;
    *(__nv_bfloat162*)&dst[kp + 1024] = h2;
}

// ---------------- big bf16 GEMM (unchanged from R4) --------------------------
__global__ void __launch_bounds__(256) gemm_bf16(int mode, const float* __restrict__ bias,
                                                 float* __restrict__ out) {
    __shared__ __nv_bfloat16 As[2][128][LDS_A];
    __shared__ __nv_bfloat16 Bs[2][128][LDS_A];
    const int tid = threadIdx.x;
    const int lane = tid & 31;
    const int warp = tid >> 5;
    const int wm = (warp & 1) * 64;
    const int wn = (warp >> 1) * 32;
    const int m0 = blockIdx.y * 128;
    const int n0 = blockIdx.x * 128;

    float acc[4][4][4];
#pragma unroll
    for (int i = 0; i < 4; i++)
#pragma unroll
        for (int j = 0; j < 4; j++)
#pragma unroll
            for (int l = 0; l < 4; l++) acc[i][j][l] = 0.f;

    const int c0row = tid >> 2, c0k = (tid & 3) * 8;
    const int c1row = (tid + 256) >> 2, c1k = ((tid + 256) & 3) * 8;
    const int a_row = wm + (lane & 15);
    const int a_koff = ((lane >> 4) << 3);
    const int b_rbase = wn + (lane & 7) + ((lane >> 4) << 3);
    const int b_koff = (((lane >> 3) & 1) << 3);

#define ISSUE(buf, kt)                                                                  \
    {                                                                                   \
        int k0 = (kt) * KT;                                                             \
        cp16(smem_u32(&As[buf][c0row][c0k]), g_abf + (size_t)(m0 + c0row) * K3 + k0 + c0k); \
        cp16(smem_u32(&As[buf][c1row][c1k]), g_abf + (size_t)(m0 + c1row) * K3 + k0 + c1k); \
        cp16(smem_u32(&Bs[buf][c0row][c0k]), g_bbf + (size_t)(n0 + c0row) * K3 + k0 + c0k); \
        cp16(smem_u32(&Bs[buf][c1row][c1k]), g_bbf + (size_t)(n0 + c1row) * K3 + k0 + c1k); \
        asm volatile("cp.async.commit_group;\n");                                       \
    }

    ISSUE(0, 0);
    int buf = 0;
    for (int kt = 0; kt < NKIT; kt++) {
        asm volatile("cp.async.wait_group 0;\n");
        __syncthreads();
        if (kt + 1 < NKIT) ISSUE(buf ^ 1, kt + 1);
#pragma unroll
        for (int ks = 0; ks < KT; ks += 16) {
            uint32_t af[4][4], bfr[2][4];
#pragma unroll
            for (int fm = 0; fm < 4; fm++) {
                uint32_t ad = smem_u32(&As[buf][fm * 16 + a_row][ks + a_koff]);
                ldsm4(af[fm][0], af[fm][1], af[fm][2], af[fm][3], ad);
            }
#pragma unroll
            for (int fn = 0; fn < 2; fn++) {
                uint32_t bd = smem_u32(&Bs[buf][fn * 16 + b_rbase][ks + b_koff]);
                ldsm4(bfr[fn][0], bfr[fn][1], bfr[fn][2], bfr[fn][3], bd);
            }
#pragma unroll
            for (int fm = 0; fm < 4; fm++)
#pragma unroll
                for (int nc = 0; nc < 4; nc++) {
                    uint32_t b0 = bfr[nc >> 1][(nc & 1) ? 2 : 0];
                    uint32_t b1 = bfr[nc >> 1][(nc & 1) ? 3 : 1];
                    mma16816(acc[fm][nc], af[fm], b0, b1);
                }
        }
        buf ^= 1;
    }

    const int r0 = lane >> 2;
    const int cp = (lane & 3) * 2;
#pragma unroll
    for (int fm = 0; fm < 4; fm++) {
#pragma unroll
        for (int nc = 0; nc < 4; nc++) {
            int m = m0 + wm + fm * 16 + r0;
            int n = n0 + wn + nc * 8 + cp;
            if (mode == 0) {
                float* dst = (n < CH) ? g_q : ((n < 2 * CH) ? g_k : g_v);
                int nn = n & (CH - 1);
                *(float2*)&dst[(size_t)m * CH + nn] = make_float2(acc[fm][nc][0], acc[fm][nc][1]);
                *(float2*)&dst[(size_t)(m + 8) * CH + nn] = make_float2(acc[fm][nc][2], acc[fm][nc][3]);
            } else {
                float2 bb = *(const float2*)&bias[n];
                *(float2*)&out[(size_t)m * CH + n] =
                    make_float2(acc[fm][nc][0] + bb.x, acc[fm][nc][1] + bb.y);
                *(float2*)&out[(size_t)(m + 8) * CH + n] =
                    make_float2(acc[fm][nc][2] + bb.x, acc[fm][nc][3] + bb.y);
            }
        }
    }
#undef ISSUE
}

// ---------------- bias precompute --------------------------------------------
__device__ __forceinline__ float resize77(const float* __restrict__ img, int y, int x) {
    float sy = (y + 0.5f) * 0.125f - 0.5f;
    float sx = (x + 0.5f) * 0.125f - 0.5f;
    int y0 = (int)floorf(sy); float fy = sy - (float)y0;
    int x0 = (int)floorf(sx); float fx = sx - (float)x0;
    int y1 = y0 + 1, x1 = x0 + 1;
    float wy0 = 1.f - fy, wy1 = fy, wx0 = 1.f - fx, wx1 = fx;
    if (y0 < 0)  { y0 = 0; wy0 = 0.f; wy1 = 1.f; }
    if (y1 > 6)  { y1 = 6; wy0 = 1.f; wy1 = 0.f; }
    if (x0 < 0)  { x0 = 0; wx0 = 0.f; wx1 = 1.f; }
    if (x1 > 6)  { x1 = 6; wx0 = 1.f; wx1 = 0.f; }
    return wy0 * (wx0 * img[y0 * 7 + x0] + wx1 * img[y0 * 7 + x1]) +
           wy1 * (wx0 * img[y1 * 7 + x0] + wx1 * img[y1 * 7 + x1]);
}
__global__ void make_bias1(const float* __restrict__ an, const float* __restrict__ ahb,
                           const float* __restrict__ awb) {
    int h = blockIdx.y, a = blockIdx.x;
    const float* img = an + (h * AG + a) * 49;
    for (int n = threadIdx.x; n < NTOK; n += blockDim.x) {
        int y = n / WWD, x = n % WWD;
        g_bias1[(h * AG + a) * NTOK + n] =
            resize77(img, y, x) + ahb[(h * AG + a) * HH + y] + awb[(h * AG + a) * WWD + x];
    }
}
__global__ void make_bias2(const float* __restrict__ na, const float* __restrict__ hab,
                           const float* __restrict__ wab) {
    int h = blockIdx.y, n = blockIdx.x;
    int y = n / WWD, x = n % WWD;
    int a = threadIdx.x;
    if (a < AG) {
        g_bias2[((size_t)h * NTOK + n) * AG + a] =
            resize77(na + (h * AG + a) * 49, y, x) + hab[(h * HH + y) * AG + a] + wab[(h * WWD + x) * AG + a];
    }
}

// ---------------- agent pooling ----------------------------------------------
__global__ void agent_pool() {
    int a = blockIdx.x, b = blockIdx.y, c = threadIdx.x;
    int ph = a / 7, pw = a % 7;
    const float* base = g_q + (size_t)b * NTOK * CH;
    float s = 0.f;
#pragma unroll
    for (int ih = 0; ih < 8; ih++)
#pragma unroll
        for (int iw = 0; iw < 8; iw++)
            s += base[(size_t)((ph * 8 + ih) * WWD + pw * 8 + iw) * CH + c];
    g_agent[(b * AG + a) * CH + c] = s * (1.0f / 64.0f);
}

// ---------------- agent-side logits (tensor core) ----------------------------
// per CTA: (n-tile 128, h, b). logits[a 0..48][n tile] = (ah*scale)·k + bias1
__global__ void __launch_bounds__(128) agent_logits_mma() {
    __shared__ __nv_bfloat16 sA0[64][72];   // ah*scale hi
    __shared__ __nv_bfloat16 sA1[64][72];   // ah*scale lo
    __shared__ __nv_bfloat16 sK[128][72];   // k term
    int b = blockIdx.z, h = blockIdx.y, n0 = blockIdx.x * 128;
    int tid = threadIdx.x, lane = tid & 31, warp = tid >> 5;

    {   // load ah*scale split (rows >=49 zero)
        int row = tid >> 1, c0 = (tid & 1) * 32;
        const float* src = g_agent + (size_t)(b * AG + row) * CH + h * HD + c0;
#pragma unroll
        for (int i = 0; i < 32; i += 2) {
            float2 v = (row < AG) ? *(const float2*)(src + i) : make_float2(0.f, 0.f);
            v.x *= 0.125f; v.y *= 0.125f;
            __nv_bfloat162 hi, lo;
            split2(v.x, hi.x, lo.x);
            split2(v.y, hi.y, lo.y);
            *(__nv_bfloat162*)&sA0[row][c0 + i] = hi;
            *(__nv_bfloat162*)&sA1[row][c0 + i] = lo;
        }
    }

    float acc[16][4];
#pragma unroll
    for (int j = 0; j < 16; j++)
#pragma unroll
        for (int e = 0; e < 4; e++) acc[j][e] = 0.f;

    for (int term = 0; term < 3; term++) {
        if (term != 1) {
            __syncthreads();
            // load k tile: hi (term 0) or lo (term 2)
            int row = tid;
            int n = n0 + row;
            const float* src = g_k + ((size_t)b * NTOK + n) * CH + h * HD;
#pragma unroll
            for (int i = 0; i < 64; i += 2) {
                float2 v = (n < NTOK) ? *(const float2*)(src + i) : make_float2(0.f, 0.f);
                __nv_bfloat162 hi;
                hi.x = __float2bfloat16(v.x);
                hi.y = __float2bfloat16(v.y);
                if (term == 0) *(__nv_bfloat162*)&sK[row][i] = hi;
                else {
                    __nv_bfloat162 lo;
                    lo.x = __float2bfloat16(v.x - __bfloat162float(hi.x));
                    lo.y = __float2bfloat16(v.y - __bfloat162float(hi.y));
                    *(__nv_bfloat162*)&sK[row][i] = lo;
                }
            }
        }
        __syncthreads();
        __nv_bfloat16 (*As)[72] = (term == 1) ? sA1 : sA0;
#pragma unroll
        for (int kt = 0; kt < 4; kt++) {
            uint32_t a_[4];
            ldsm4(a_[0], a_[1], a_[2], a_[3],
                  smem_u32(&As[warp * 16 + (lane & 15)][kt * 16 + ((lane >> 4) << 3)]));
#pragma unroll
            for (int p = 0; p < 8; p++) {
                uint32_t br[4];
                ldsm4(br[0], br[1], br[2], br[3],
                      smem_u32(&sK[p * 16 + (lane & 7) + ((lane >> 4) << 3)][kt * 16 + (((lane >> 3) & 1) << 3)]));
                mma16816(acc[p * 2],     a_, br[0], br[1]);
                mma16816(acc[p * 2 + 1], a_, br[2], br[3]);
            }
        }
    }

    // epilogue: + bias1 -> g_logits
    int abase = warp * 16 + (lane >> 2);
#pragma unroll
    for (int rh = 0; rh < 2; rh++) {
        int aa = abase + rh * 8;
        if (aa < AG) {
            float* dst = g_logits + ((size_t)(b * NH + h) * AG + aa) * NTOK;
            const float* b1p = g_bias1 + (size_t)(h * AG + aa) * NTOK;
#pragma unroll
            for (int j = 0; j < 16; j++) {
                int n = n0 + j * 8 + (lane & 3) * 2;
                if (n < NTOK) {
                    float2 bb = *(const float2*)(b1p + n);
                    *(float2*)(dst + n) = make_float2(acc[j][rh * 2] + bb.x, acc[j][rh * 2 + 1] + bb.y);
                }
            }
        }
    }
}

// ---------------- softmax over n=3136 ----------------------------------------
__global__ void softmax_rows() {
    int r = blockIdx.x;
    float* row = g_logits + (size_t)r * NTOK;
    __shared__ float red[128];
    int tid = threadIdx.x;
    float m = -1e30f;
    for (int i = tid; i < NTOK; i += 128) m = fmaxf(m, row[i]);
    red[tid] = m; __syncthreads();
    for (int s = 64; s > 0; s >>= 1) { if (tid < s) red[tid] = fmaxf(red[tid], red[tid + s]); __syncthreads(); }
    m = red[0]; __syncthreads();
    float sum = 0.f;
    for (int i = tid; i < NTOK; i += 128) { float e = __expf(row[i] - m); row[i] = e; sum += e; }
    red[tid] = sum; __syncthreads();
    for (int s = 64; s > 0; s >>= 1) { if (tid < s) red[tid] += red[tid + s]; __syncthreads(); }
    float inv = 1.0f / red[0];
    for (int i = tid; i < NTOK; i += 128) row[i] *= inv;
}

__global__ void zero_agentv() {
    int i = blockIdx.x * 256 + threadIdx.x;
    if (i < BQ * NH * AG * HD) g_agentv[i] = 0.f;
}

// ---------------- agent_v = attn @ v (tensor core, k-split + atomics) --------
__global__ void __launch_bounds__(128) agent_v_mma() {
    __shared__ __nv_bfloat16 sP0[64][72], sP1[64][72];
    __shared__ __nv_bfloat16 sV0[64][72], sV1[64][72];
    int ks = blockIdx.x, h = blockIdx.y, b = blockIdx.z;
    int bh = b * NH + h;
    int tid = threadIdx.x, lane = tid & 31, warp = tid >> 5;

    float acc[8][4];
#pragma unroll
    for (int j = 0; j < 8; j++)
#pragma unroll
        for (int e = 0; e < 4; e++) acc[j][e] = 0.f;

    for (int it = 0; it < 7; it++) {
        int n0 = ks * 448 + it * 64;
        __syncthreads();
        {   // P tile [a 64][n 64] split
            int a = tid >> 1, c0 = (tid & 1) * 32;
            const float* src = g_logits + ((size_t)bh * AG + a) * NTOK + n0 + c0;
#pragma unroll
            for (int i = 0; i < 32; i += 2) {
                float2 v = (a < AG) ? *(const float2*)(src + i) : make_float2(0.f, 0.f);
                __nv_bfloat162 hi, lo;
                split2(v.x, hi.x, lo.x);
                split2(v.y, hi.y, lo.y);
                *(__nv_bfloat162*)&sP0[a][c0 + i] = hi;
                *(__nv_bfloat162*)&sP1[a][c0 + i] = lo;
            }
        }
        {   // V tile [n 64][d 64] split
            int r = tid >> 1, c0 = (tid & 1) * 32;
            const float* src = g_v + ((size_t)b * NTOK + n0 + r) * CH + h * HD + c0;
#pragma unroll
            for (int i = 0; i < 32; i += 2) {
                float2 v = *(const float2*)(src + i);
                __nv_bfloat162 hi, lo;
                split2(v.x, hi.x, lo.x);
                split2(v.y, hi.y, lo.y);
                *(__nv_bfloat162*)&sV0[r][c0 + i] = hi;
                *(__nv_bfloat162*)&sV1[r][c0 + i] = lo;
            }
        }
        __syncthreads();
#pragma unroll
        for (int kt = 0; kt < 4; kt++) {
            uint32_t ph_[4], pl_[4];
            uint32_t arow = warp * 16 + (lane & 15);
            uint32_t acol = kt * 16 + ((lane >> 4) << 3);
            ldsm4(ph_[0], ph_[1], ph_[2], ph_[3], smem_u32(&sP0[arow][acol]));
            ldsm4(pl_[0], pl_[1], pl_[2], pl_[3], smem_u32(&sP1[arow][acol]));
#pragma unroll
            for (int dp = 0; dp < 4; dp++) {
                uint32_t bh_[4], bl_[4];
                uint32_t brow = kt * 16 + (lane & 15);
                uint32_t bcol = dp * 16 + ((lane >> 4) << 3);
                ldsm4t(bh_[0], bh_[1], bh_[2], bh_[3], smem_u32(&sV0[brow][bcol]));
                ldsm4t(bl_[0], bl_[1], bl_[2], bl_[3], smem_u32(&sV1[brow][bcol]));
                mma16816(acc[dp * 2], ph_, bh_[0], bh_[1]);
                mma16816(acc[dp * 2], ph_, bl_[0], bl_[1]);
                mma16816(acc[dp * 2], pl_, bh_[0], bh_[1]);
                mma16816(acc[dp * 2 + 1], ph_, bh_[2], bh_[3]);
                mma16816(acc[dp * 2 + 1], ph_, bl_[2], bl_[3]);
                mma16816(acc[dp * 2 + 1], pl_, bh_[2], bh_[3]);
            }
        }
    }

    int abase = warp * 16 + (lane >> 2);
#pragma unroll
    for (int rh = 0; rh < 2; rh++) {
        int aa = abase + rh * 8;
        if (aa < AG) {
            float* dst = g_agentv + ((size_t)bh * AG + aa) * HD;
#pragma unroll
            for (int j = 0; j < 8; j++) {
                int d = j * 8 + (lane & 3) * 2;
                atomicAdd(dst + d,     acc[j][rh * 2]);
                atomicAdd(dst + d + 1, acc[j][rh * 2 + 1]);
            }
        }
    }
}

// ---------------- q-side fused flash (tensor core) ---------------------------
__global__ void __launch_bounds__(128) qside_mma() {
    __shared__ __nv_bfloat16 sQ[128][72];
    __shared__ __nv_bfloat16 sB0[64][72];   // ah*scale hi -> later agent_v hi
    __shared__ __nv_bfloat16 sB1[64][72];   // lo
    int b = blockIdx.z, h = blockIdx.y, m0 = blockIdx.x * 128;
    int tid = threadIdx.x, lane = tid & 31, warp = tid >> 5;

    {   // ah*scale split
        int row = tid >> 1, c0 = (tid & 1) * 32;
        const float* src = g_agent + (size_t)(b * AG + row) * CH + h * HD + c0;
#pragma unroll
        for (int i = 0; i < 32; i += 2) {
            float2 v = (row < AG) ? *(const float2*)(src + i) : make_float2(0.f, 0.f);
            v.x *= 0.125f; v.y *= 0.125f;
            __nv_bfloat162 hi, lo;
            split2(v.x, hi.x, lo.x);
            split2(v.y, hi.y, lo.y);
            *(__nv_bfloat162*)&sB0[row][c0 + i] = hi;
            *(__nv_bfloat162*)&sB1[row][c0 + i] = lo;
        }
    }

    float acc[2][8][4];
#pragma unroll
    for (int mf = 0; mf < 2; mf++)
#pragma unroll
        for (int j = 0; j < 8; j++)
#pragma unroll
            for (int e = 0; e < 4; e++) acc[mf][j][e] = 0.f;

    // ---- phase 1: logits = q*scale? (scale folded into ah) -----------------
    for (int term = 0; term < 3; term++) {
        if (term != 1) {
            __syncthreads();
            int row = tid;
            int m = m0 + row;
            const float* src = g_q + ((size_t)b * NTOK + m) * CH + h * HD;
#pragma unroll
            for (int i = 0; i < 64; i += 2) {
                float2 v = (m < NTOK) ? *(const float2*)(src + i) : make_float2(0.f, 0.f);
                __nv_bfloat162 hi;
                hi.x = __float2bfloat16(v.x);
                hi.y = __float2bfloat16(v.y);
                if (term == 0) *(__nv_bfloat162*)&sQ[row][i] = hi;
                else {
                    __nv_bfloat162 lo;
                    lo.x = __float2bfloat16(v.x - __bfloat162float(hi.x));
                    lo.y = __float2bfloat16(v.y - __bfloat162float(hi.y));
                    *(__nv_bfloat162*)&sQ[row][i] = lo;
                }
            }
        }
        __syncthreads();
        __nv_bfloat16 (*Bs)[72] = (term == 1) ? sB1 : sB0;
#pragma unroll
        for (int kt = 0; kt < 4; kt++) {
            uint32_t af[2][4];
#pragma unroll
            for (int mf = 0; mf < 2; mf++)
                ldsm4(af[mf][0], af[mf][1], af[mf][2], af[mf][3],
                      smem_u32(&sQ[warp * 32 + mf * 16 + (lane & 15)][kt * 16 + ((lane >> 4) << 3)]));
#pragma unroll
            for (int p = 0; p < 4; p++) {
                uint32_t br[4];
                ldsm4(br[0], br[1], br[2], br[3],
                      smem_u32(&Bs[p * 16 + (lane & 7) + ((lane >> 4) << 3)][kt * 16 + (((lane >> 3) & 1) << 3)]));
#pragma unroll
                for (int mf = 0; mf < 2; mf++) {
                    mma16816(acc[mf][p * 2],     af[mf], br[0], br[1]);
                    mma16816(acc[mf][p * 2 + 1], af[mf], br[2], br[3]);
                }
            }
        }
    }
    __syncthreads();   // all mma done; safe to reuse sB0/sB1

    {   // load agent_v split into sB0/sB1
        int row = tid >> 1, c0 = (tid & 1) * 32;
        const float* src = g_agentv + ((size_t)(b * NH + h) * AG + row) * HD + c0;
#pragma unroll
        for (int i = 0; i < 32; i += 2) {
            float2 v = (row < AG) ? *(const float2*)(src + i) : make_float2(0.f, 0.f);
            __nv_bfloat162 hi, lo;
            split2(v.x, hi.x, lo.x);
            split2(v.y, hi.y, lo.y);
            *(__nv_bfloat162*)&sB0[row][c0 + i] = hi;
            *(__nv_bfloat162*)&sB1[row][c0 + i] = lo;
        }
    }

    // ---- softmax over a (49) in registers ----------------------------------
    float inv[2][2];
#pragma unroll
    for (int mf = 0; mf < 2; mf++) {
#pragma unroll
        for (int rh = 0; rh < 2; rh++) {
            int m = m0 + warp * 32 + mf * 16 + (lane >> 2) + rh * 8;
            const float* b2 = g_bias2 + ((size_t)h * NTOK + (m < NTOK ? m : 0)) * AG;
            float mx = -1e30f;
#pragma unroll
            for (int j = 0; j < 8; j++)
#pragma unroll
                for (int e = 0; e < 2; e++) {
                    int a = j * 8 + (lane & 3) * 2 + e;
                    float v;
                    if (a < AG) v = acc[mf][j][rh * 2 + e] + ((m < NTOK) ? b2[a] : 0.f);
                    else v = -1e30f;
                    acc[mf][j][rh * 2 + e] = v;
                    mx = fmaxf(mx, v);
                }
            mx = fmaxf(mx, __shfl_xor_sync(0xffffffffu, mx, 1));
            mx = fmaxf(mx, __shfl_xor_sync(0xffffffffu, mx, 2));
            float s = 0.f;
#pragma unroll
            for (int j = 0; j < 8; j++)
#pragma unroll
                for (int e = 0; e < 2; e++) {
                    float ev = __expf(acc[mf][j][rh * 2 + e] - mx);
                    acc[mf][j][rh * 2 + e] = ev;
                    s += ev;
                }
            s += __shfl_xor_sync(0xffffffffu, s, 1);
            s += __shfl_xor_sync(0xffffffffu, s, 2);
            inv[mf][rh] = 1.0f / s;
        }
    }
    __syncthreads();   // agent_v smem visible

    // ---- phase 2: out = P @ agent_v  (P in registers as A-frags) ------------
    float o[2][8][4];
#pragma unroll
    for (int mf = 0; mf < 2; mf++)
#pragma unroll
        for (int j = 0; j < 8; j++)
#pragma unroll
            for (int e = 0; e < 4; e++) o[mf][j][e] = 0.f;

#pragma unroll
    for (int kt = 0; kt < 4; kt++) {
        uint32_t ah_[2][4], al_[2][4];
#pragma unroll
        for (int mf = 0; mf < 2; mf++)
#pragma unroll
            for (int q = 0; q < 2; q++) {
                int j = kt * 2 + q;
#pragma unroll
                for (int rh = 0; rh < 2; rh++) {
                    float v0 = acc[mf][j][rh * 2 + 0] * inv[mf][rh];
                    float v1 = acc[mf][j][rh * 2 + 1] * inv[mf][rh];
                    __nv_bfloat16 h0, l0, h1, l1;
                    split2(v0, h0, l0);
                    split2(v1, h1, l1);
                    ah_[mf][q * 2 + rh] = pack_bf2(h0, h1);
                    al_[mf][q * 2 + rh] = pack_bf2(l0, l1);
                }
            }
#pragma unroll
        for (int dp = 0; dp < 4; dp++) {
            uint32_t bh_[4], bl_[4];
            uint32_t brow = kt * 16 + (lane & 15);
            uint32_t bcol = dp * 16 + ((lane >> 4) << 3);
            ldsm4t(bh_[0], bh_[1], bh_[2], bh_[3], smem_u32(&sB0[brow][bcol]));
            ldsm4t(bl_[0], bl_[1], bl_[2], bl_[3], smem_u32(&sB1[brow][bcol]));
#pragma unroll
            for (int mf = 0; mf < 2; mf++) {
                mma16816(o[mf][dp * 2], ah_[mf], bh_[0], bh_[1]);
                mma16816(o[mf][dp * 2], ah_[mf], bl_[0], bl_[1]);
                mma16816(o[mf][dp * 2], al_[mf], bh_[0], bh_[1]);
                mma16816(o[mf][dp * 2 + 1], ah_[mf], bh_[2], bh_[3]);
                mma16816(o[mf][dp * 2 + 1], ah_[mf], bl_[2], bl_[3]);
                mma16816(o[mf][dp * 2 + 1], al_[mf], bh_[2], bh_[3]);
            }
        }
    }

    // store to g_pre
#pragma unroll
    for (int mf = 0; mf < 2; mf++) {
#pragma unroll
        for (int j = 0; j < 8; j++) {
            int m = m0 + warp * 32 + mf * 16 + (lane >> 2);
            int d = j * 8 + (lane & 3) * 2;
            float* dst = g_pre + ((size_t)b * NTOK + m) * CH + h * HD + d;
            if (m < NTOK)
                *(float2*)dst = make_float2(o[mf][j][0], o[mf][j][1]);
            if (m + 8 < NTOK)
                *(float2*)(dst + 8 * CH) = make_float2(o[mf][j][2], o[mf][j][3]);
        }
    }
}

// ---------------- depthwise 3x3 conv on v, accumulate into g_pre -------------
__global__ void dwc_kern(const float* __restrict__ w, const float* __restrict__ bias) {
    long long i = (long long)blockIdx.x * 256 + threadIdx.x;
    if (i >= (long long)MROWS * (CH / 4)) return;
    int c = (int)(i & (CH / 4 - 1)) << 2;
    long long rown = i >> 7;
    int n = (int)(rown % NTOK);
    int b = (int)(rown / NTOK);
    int y = n / WWD, x = n % WWD;
    float a0 = bias[c], a1 = bias[c + 1], a2 = bias[c + 2], a3 = bias[c + 3];
#pragma unroll
    for (int ky = 0; ky < 3; ky++) {
        int yy = y + ky - 1;
        if (yy < 0 || yy >= HH) continue;
#pragma unroll
        for (int kx = 0; kx < 3; kx++) {
            int xx = x + kx - 1;
            if (xx < 0 || xx >= WWD) continue;
            float4 vv = *(const float4*)&g_v[((size_t)b * NTOK + yy * WWD + xx) * CH + c];
            int ki = ky * 3 + kx;
            a0 = fmaf(vv.x, w[(c + 0) * 9 + ki], a0);
            a1 = fmaf(vv.y, w[(c + 1) * 9 + ki], a1);
            a2 = fmaf(vv.z, w[(c + 2) * 9 + ki], a2);
            a3 = fmaf(vv.w, w[(c + 3) * 9 + ki], a3);
        }
    }
    float4* dst = (float4*)&g_pre[(size_t)rown * CH + c];
    float4 cur = *dst;
    cur.x += a0; cur.y += a1; cur.z += a2; cur.w += a3;
    *dst = cur;
}

// ---------------- launch ------------------------------------------------------
extern "C" void kernel_launch(void* const* d_in, const int* in_sizes, int n_in,
                              void* d_out, int out_size) {
    int off = (in_sizes[1] == 1) ? 3 : 1;
    const float* x      = (const float*)d_in[0];
    const float* q_w    = (const float*)d_in[off + 0];
    const float* kv_w   = (const float*)d_in[off + 1];
    const float* proj_w = (const float*)d_in[off + 2];
    const float* proj_b = (const float*)d_in[off + 3];
    const float* dwc_w  = (const float*)d_in[off + 4];
    const float* dwc_b  = (const float*)d_in[off + 5];
    const float* an_b   = (const float*)d_in[off + 6];
    const float* na_b   = (const float*)d_in[off + 7];
    const float* ah_b   = (const float*)d_in[off + 8];
    const float* aw_b   = (const float*)d_in[off + 9];
    const float* ha_b   = (const float*)d_in[off + 10];
    const float* wa_b   = (const float*)d_in[off + 11];
    float* out = (float*)d_out;

    make_bias1<<<dim3(AG, NH), 256>>>(an_b, ah_b, aw_b);
    make_bias2<<<dim3(NTOK, NH), 64>>>(na_b, ha_b, wa_b);
    zero_agentv<<<(BQ * NH * AG * HD + 255) / 256, 256>>>();

    pack_a<<<MROWS, 256>>>(x, 0);
    pack_b<<<3 * CH, 256>>>(q_w, kv_w, 1);
    gemm_bf16<<<dim3(1536 / 128, MROWS / 128), 256>>>(0, nullptr, nullptr);

    agent_pool<<<dim3(AG, BQ), CH>>>();
    agent_logits_mma<<<dim3(25, NH, BQ), 128>>>();
    softmax_rows<<<BQ * NH * AG, 128>>>();
    agent_v_mma<<<dim3(7, NH, BQ), 128>>>();
    qside_mma<<<dim3(25, NH, BQ), 128>>>();
    dwc_kern<<<(int)(((long long)MROWS * (CH / 4) + 255) / 256), 256>>>(dwc_w, dwc_b);

    pack_a<<<MROWS, 256>>>(nullptr, 1);
    pack_b<<<CH, 256>>>(proj_w, nullptr, 0);
    gemm_bf16<<<dim3(CH / 128, MROWS / 128), 256>>>(1, proj_b, out);
}

// round 10
// speedup vs baseline: 2.1368x; 1.0960x over previous
#include <cuda_runtime.h>
#include <cuda_bf16.h>
#include <math.h>
#include <stdint.h>

#define BQ 16
#define CH 512
#define HH 56
#define WWD 56
#define NTOK 3136          // 56*56
#define NH 8
#define HD 64
#define AG 49
#define MROWS (BQ*NTOK)    // 50176
#define K2 1024            // packed K: [hi(512) | lo(512)]
#define NKIT 16            // 512 / 32 k-chunks

// ---------------- scratch ----------------------------------------------------
__device__ float g_q[(size_t)MROWS * CH];
__device__ float g_k[(size_t)MROWS * CH];
__device__ float g_v[(size_t)MROWS * CH];
__device__ float g_pre[(size_t)MROWS * CH];
__device__ float g_agent[BQ * AG * CH];
__device__ float g_bias1[NH * AG * NTOK];          // [h][a][n]
__device__ float g_bias2[(size_t)NH * NTOK * AG];  // [h][n][a]
__device__ float g_agentv[BQ * NH * AG * HD];
__device__ __nv_bfloat16 g_abf[(size_t)MROWS * K2];
__device__ __nv_bfloat16 g_bbf[(size_t)3 * CH * K2];

// ---------------- helpers ----------------------------------------------------
__device__ __forceinline__ void split2(float v, __nv_bfloat16& hi, __nv_bfloat16& lo) {
    hi = __float2bfloat16(v);
    lo = __float2bfloat16(v - __bfloat162float(hi));
}
__device__ __forceinline__ uint32_t pack_bf2(__nv_bfloat16 a, __nv_bfloat16 b) {
    return ((uint32_t)__bfloat16_as_ushort(b) << 16) | (uint32_t)__bfloat16_as_ushort(a);
}
__device__ __forceinline__ uint32_t smem_u32(const void* p) {
    return (uint32_t)__cvta_generic_to_shared(p);
}
__device__ __forceinline__ void ldsm4(uint32_t& r0, uint32_t& r1, uint32_t& r2, uint32_t& r3, uint32_t addr) {
    asm volatile("ldmatrix.sync.aligned.m8n8.x4.shared.b16 {%0,%1,%2,%3}, [%4];"
                 : "=r"(r0), "=r"(r1), "=r"(r2), "=r"(r3) : "r"(addr));
}
__device__ __forceinline__ void ldsm4t(uint32_t& r0, uint32_t& r1, uint32_t& r2, uint32_t& r3, uint32_t addr) {
    asm volatile("ldmatrix.sync.aligned.m8n8.x4.trans.shared.b16 {%0,%1,%2,%3}, [%4];"
                 : "=r"(r0), "=r"(r1), "=r"(r2), "=r"(r3) : "r"(addr));
}
__device__ __forceinline__ void mma16816(float* c, const uint32_t* a, uint32_t b0, uint32_t b1) {
    asm volatile("mma.sync.aligned.m16n8k16.row.col.f32.bf16.bf16.f32 "
                 "{%0,%1,%2,%3}, {%4,%5,%6,%7}, {%8,%9}, {%0,%1,%2,%3};"
                 : "+f"(c[0]), "+f"(c[1]), "+f"(c[2]), "+f"(c[3])
                 : "r"(a[0]), "r"(a[1]), "r"(a[2]), "r"(a[3]), "r"(b0), "r"(b1));
}
__device__ __forceinline__ void cp16(uint32_t sp, const void* gp) {
    asm volatile("cp.async.cg.shared.global [%0], [%1], 16;\n" :: "r"(sp), "l"(gp));
}

// ---------------- pack kernels -----------------------------------------------
// A pack: [M][512] fp32 -> [M][1024] = [hi | lo]
__global__ void pack_a(const float* __restrict__ src) {
    int row = blockIdx.x;
    int kp = threadIdx.x * 2;
    float2 v = *(const float2*)&src[(size_t)row * CH + kp];
    __nv_bfloat162 h2, l2;
    split2(v.x, h2.x, l2.x);
    split2(v.y, h2.y, l2.y);
    __nv_bfloat16* dst = g_abf + (size_t)row * K2;
    *(__nv_bfloat162*)&dst[kp]       = h2;
    *(__nv_bfloat162*)&dst[kp + 512] = l2;
}
// A pack for proj, fused with depthwise conv: val = g_pre + dwc(v) + dwc_b
__global__ void pack_a_dwc(const float* __restrict__ w, const float* __restrict__ dbias) {
    int row = blockIdx.x;           // b*3136 + n
    int c = threadIdx.x * 2;
    int n = row % NTOK, b = row / NTOK;
    int y = n / WWD, x = n % WWD;
    float a0 = dbias[c], a1 = dbias[c + 1];
#pragma unroll
    for (int ky = 0; ky < 3; ky++) {
        int yy = y + ky - 1;
        if (yy < 0 || yy >= HH) continue;
#pragma unroll
        for (int kx = 0; kx < 3; kx++) {
            int xx = x + kx - 1;
            if (xx < 0 || xx >= WWD) continue;
            float2 vv = *(const float2*)&g_v[((size_t)b * NTOK + yy * WWD + xx) * CH + c];
            int ki = ky * 3 + kx;
            a0 = fmaf(vv.x, w[c * 9 + ki], a0);
            a1 = fmaf(vv.y, w[(c + 1) * 9 + ki], a1);
        }
    }
    float2 p = *(const float2*)&g_pre[(size_t)row * CH + c];
    float v0 = p.x + a0, v1 = p.y + a1;
    __nv_bfloat162 h2, l2;
    split2(v0, h2.x, l2.x);
    split2(v1, h2.y, l2.y);
    __nv_bfloat16* dst = g_abf + (size_t)row * K2;
    *(__nv_bfloat162*)&dst[c]       = h2;
    *(__nv_bfloat162*)&dst[c + 512] = l2;
}
// B pack: rows -> [1024] = [hi | lo]. qkv: 1536 rows from q_w/kv_w; else 512 rows w0.
__global__ void pack_b(const float* __restrict__ w0, const float* __restrict__ w1, int qkv) {
    int row = blockIdx.x;
    int kp = threadIdx.x * 2;
    const float* src;
    if (qkv) src = (row < CH) ? (w0 + (size_t)row * CH) : (w1 + (size_t)(row - CH) * CH);
    else     src = w0 + (size_t)row * CH;
    float2 v = *(const float2*)&src[kp];
    __nv_bfloat162 h2, l2;
    split2(v.x, h2.x, l2.x);
    split2(v.y, h2.y, l2.y);
    __nv_bfloat16* dst = g_bbf + (size_t)row * K2;
    *(__nv_bfloat162*)&dst[kp]       = h2;
    *(__nv_bfloat162*)&dst[kp + 512] = l2;
}

// ---------------- split bf16 GEMM: C = Ah*Bh + Ah*Bl + Al*Bh ------------------
// 128x128 tile, 256 thr, 32-wide k-chunks, 3-stage cp.async, Bh frag reuse.
#define OPS (128 * 40)
#define GS_DYN (3 * 4 * OPS * 2)
__global__ void __launch_bounds__(256) gemm_split(int mode, const float* __restrict__ bias,
                                                  float* __restrict__ out) {
    extern __shared__ __nv_bfloat16 smg[];
    const int tid = threadIdx.x;
    const int lane = tid & 31;
    const int warp = tid >> 5;
    const int wm = (warp & 1) * 64;
    const int wn = (warp >> 1) * 32;
    const int m0 = blockIdx.y * 128;
    const int n0 = blockIdx.x * 128;
    const uint32_t sb = smem_u32(smg);

    float acc[4][4][4];
#pragma unroll
    for (int i = 0; i < 4; i++)
#pragma unroll
        for (int j = 0; j < 4; j++)
#pragma unroll
            for (int l = 0; l < 4; l++) acc[i][j][l] = 0.f;

#define ISSUE(st, ch)                                                                     \
    {                                                                                     \
        uint32_t bse = (uint32_t)(st) * (4 * OPS);                                        \
        _Pragma("unroll")                                                                 \
        for (int it = 0; it < 2; it++) {                                                  \
            int id = it * 256 + tid;                                                      \
            int row = id >> 2;                                                            \
            int c8 = (id & 3) * 8;                                                        \
            int k = (ch) * 32 + c8;                                                       \
            cp16(sb + (bse + row * 40 + c8) * 2,           g_abf + (size_t)(m0 + row) * K2 + k);        \
            cp16(sb + (bse + OPS + row * 40 + c8) * 2,     g_abf + (size_t)(m0 + row) * K2 + 512 + k);  \
            cp16(sb + (bse + 2 * OPS + row * 40 + c8) * 2, g_bbf + (size_t)(n0 + row) * K2 + k);        \
            cp16(sb + (bse + 3 * OPS + row * 40 + c8) * 2, g_bbf + (size_t)(n0 + row) * K2 + 512 + k);  \
        }                                                                                 \
        asm volatile("cp.async.commit_group;\n");                                         \
    }

    ISSUE(0, 0);
    ISSUE(1, 1);
    for (int c = 0; c < NKIT; c++) {
        if (c + 1 < NKIT) asm volatile("cp.async.wait_group 1;\n");
        else              asm volatile("cp.async.wait_group 0;\n");
        __syncthreads();
        if (c + 2 < NKIT) ISSUE((c + 2) % 3, c + 2);
        uint32_t bse = (uint32_t)(c % 3) * (4 * OPS);
#pragma unroll
        for (int ks = 0; ks < 32; ks += 16) {
            uint32_t a_h[4][4], a_l[4][4];
#pragma unroll
            for (int fm = 0; fm < 4; fm++) {
                uint32_t ro = (uint32_t)((wm + fm * 16 + (lane & 15)) * 40 + ks + ((lane >> 4) << 3));
                ldsm4(a_h[fm][0], a_h[fm][1], a_h[fm][2], a_h[fm][3], sb + (bse + ro) * 2);
                ldsm4(a_l[fm][0], a_l[fm][1], a_l[fm][2], a_l[fm][3], sb + (bse + OPS + ro) * 2);
            }
#pragma unroll
            for (int fn = 0; fn < 2; fn++) {
                uint32_t ro = (uint32_t)((wn + fn * 16 + (lane & 7) + ((lane >> 4) << 3)) * 40
                                         + ks + (((lane >> 3) & 1) << 3));
                uint32_t bh[4], bl[4];
                ldsm4(bh[0], bh[1], bh[2], bh[3], sb + (bse + 2 * OPS + ro) * 2);
                ldsm4(bl[0], bl[1], bl[2], bl[3], sb + (bse + 3 * OPS + ro) * 2);
#pragma unroll
                for (int q = 0; q < 2; q++) {
                    int nc = fn * 2 + q;
                    uint32_t b0h = bh[q ? 2 : 0], b1h = bh[q ? 3 : 1];
                    uint32_t b0l = bl[q ? 2 : 0], b1l = bl[q ? 3 : 1];
#pragma unroll
                    for (int fm = 0; fm < 4; fm++) {
                        mma16816(acc[fm][nc], a_h[fm], b0h, b1h);
                        mma16816(acc[fm][nc], a_h[fm], b0l, b1l);
                        mma16816(acc[fm][nc], a_l[fm], b0h, b1h);
                    }
                }
            }
        }
    }

    const int r0 = lane >> 2;
    const int cp = (lane & 3) * 2;
#pragma unroll
    for (int fm = 0; fm < 4; fm++) {
#pragma unroll
        for (int nc = 0; nc < 4; nc++) {
            int m = m0 + wm + fm * 16 + r0;
            int n = n0 + wn + nc * 8 + cp;
            if (mode == 0) {
                float* dst = (n < CH) ? g_q : ((n < 2 * CH) ? g_k : g_v);
                int nn = n & (CH - 1);
                *(float2*)&dst[(size_t)m * CH + nn] = make_float2(acc[fm][nc][0], acc[fm][nc][1]);
                *(float2*)&dst[(size_t)(m + 8) * CH + nn] = make_float2(acc[fm][nc][2], acc[fm][nc][3]);
            } else {
                float2 bb = *(const float2*)&bias[n];
                *(float2*)&out[(size_t)m * CH + n] =
                    make_float2(acc[fm][nc][0] + bb.x, acc[fm][nc][1] + bb.y);
                *(float2*)&out[(size_t)(m + 8) * CH + n] =
                    make_float2(acc[fm][nc][2] + bb.x, acc[fm][nc][3] + bb.y);
            }
        }
    }
#undef ISSUE
}

// ---------------- bias precompute --------------------------------------------
__device__ __forceinline__ float resize77(const float* __restrict__ img, int y, int x) {
    float sy = (y + 0.5f) * 0.125f - 0.5f;
    float sx = (x + 0.5f) * 0.125f - 0.5f;
    int y0 = (int)floorf(sy); float fy = sy - (float)y0;
    int x0 = (int)floorf(sx); float fx = sx - (float)x0;
    int y1 = y0 + 1, x1 = x0 + 1;
    float wy0 = 1.f - fy, wy1 = fy, wx0 = 1.f - fx, wx1 = fx;
    if (y0 < 0)  { y0 = 0; wy0 = 0.f; wy1 = 1.f; }
    if (y1 > 6)  { y1 = 6; wy0 = 1.f; wy1 = 0.f; }
    if (x0 < 0)  { x0 = 0; wx0 = 0.f; wx1 = 1.f; }
    if (x1 > 6)  { x1 = 6; wx0 = 1.f; wx1 = 0.f; }
    return wy0 * (wx0 * img[y0 * 7 + x0] + wx1 * img[y0 * 7 + x1]) +
           wy1 * (wx0 * img[y1 * 7 + x0] + wx1 * img[y1 * 7 + x1]);
}
__global__ void make_bias1(const float* __restrict__ an, const float* __restrict__ ahb,
                           const float* __restrict__ awb) {
    int h = blockIdx.y, a = blockIdx.x;
    const float* img = an + (h * AG + a) * 49;
    for (int n = threadIdx.x; n < NTOK; n += blockDim.x) {
        int y = n / WWD, x = n % WWD;
        g_bias1[(h * AG + a) * NTOK + n] =
            resize77(img, y, x) + ahb[(h * AG + a) * HH + y] + awb[(h * AG + a) * WWD + x];
    }
}
__global__ void make_bias2(const float* __restrict__ na, const float* __restrict__ hab,
                           const float* __restrict__ wab) {
    int h = blockIdx.y, n = blockIdx.x;
    int y = n / WWD, x = n % WWD;
    int a = threadIdx.x;
    if (a < AG) {
        g_bias2[((size_t)h * NTOK + n) * AG + a] =
            resize77(na + (h * AG + a) * 49, y, x) + hab[(h * HH + y) * AG + a] + wab[(h * WWD + x) * AG + a];
    }
}

// ---------------- agent pooling ----------------------------------------------
__global__ void agent_pool() {
    int a = blockIdx.x, b = blockIdx.y, c = threadIdx.x;
    int ph = a / 7, pw = a % 7;
    const float* base = g_q + (size_t)b * NTOK * CH;
    float s = 0.f;
#pragma unroll
    for (int ih = 0; ih < 8; ih++)
#pragma unroll
        for (int iw = 0; iw < 8; iw++)
            s += base[(size_t)((ph * 8 + ih) * WWD + pw * 8 + iw) * CH + c];
    g_agent[(b * AG + a) * CH + c] = s * (1.0f / 64.0f);
}

// ---------------- fused agent-side flash attention ----------------------------
// Per (h, b): agent_v[49][64] = softmax_n(ah*scale . k^T + bias1) @ v, online.
#define AF_DYN ((64 + 64 + 128 + 128 + 128 + 128) * 72 * 2)
__global__ void __launch_bounds__(128) agent_fused() {
    extern __shared__ __nv_bfloat16 smf[];
    __nv_bfloat16 (*sA0)[72] = (__nv_bfloat16(*)[72])smf;
    __nv_bfloat16 (*sA1)[72] = sA0 + 64;
    __nv_bfloat16 (*sK0)[72] = sA1 + 64;
    __nv_bfloat16 (*sK1)[72] = sK0 + 128;
    __nv_bfloat16 (*sV0)[72] = sK1 + 128;
    __nv_bfloat16 (*sV1)[72] = sV0 + 128;
    int h = blockIdx.x, b = blockIdx.y;
    int bh = b * NH + h;
    int tid = threadIdx.x, lane = tid & 31, warp = tid >> 5;

    {   // ah*scale split (rows >= 49 zero)
        int row = tid >> 1, c0 = (tid & 1) * 32;
        const float* src = g_agent + (size_t)(b * AG + row) * CH + h * HD + c0;
#pragma unroll
        for (int i = 0; i < 32; i += 2) {
            float2 v = (row < AG) ? *(const float2*)(src + i) : make_float2(0.f, 0.f);
            v.x *= 0.125f; v.y *= 0.125f;
            __nv_bfloat162 hi, lo;
            split2(v.x, hi.x, lo.x);
            split2(v.y, hi.y, lo.y);
            *(__nv_bfloat162*)&sA0[row][c0 + i] = hi;
            *(__nv_bfloat162*)&sA1[row][c0 + i] = lo;
        }
    }

    float m_run[2] = {-1e30f, -1e30f};
    float l_run[2] = {0.f, 0.f};
    float o[8][4];
#pragma unroll
    for (int j = 0; j < 8; j++)
#pragma unroll
        for (int e = 0; e < 4; e++) o[j][e] = 0.f;

    for (int t = 0; t < 25; t++) {
        int n0 = t * 128;
        __syncthreads();
        {   // load k,v tiles (128 rows x 64 cols), split hi/lo
            int n = n0 + tid;
            bool valid = (n < NTOK);
            const float* ksrc = g_k + ((size_t)b * NTOK + (valid ? n : 0)) * CH + h * HD;
            const float* vsrc = g_v + ((size_t)b * NTOK + (valid ? n : 0)) * CH + h * HD;
#pragma unroll
            for (int i = 0; i < 64; i += 2) {
                float2 kv = valid ? *(const float2*)(ksrc + i) : make_float2(0.f, 0.f);
                float2 vv = valid ? *(const float2*)(vsrc + i) : make_float2(0.f, 0.f);
                __nv_bfloat162 khi, klo, vhi, vlo;
                split2(kv.x, khi.x, klo.x); split2(kv.y, khi.y, klo.y);
                split2(vv.x, vhi.x, vlo.x); split2(vv.y, vhi.y, vlo.y);
                *(__nv_bfloat162*)&sK0[tid][i] = khi;
                *(__nv_bfloat162*)&sK1[tid][i] = klo;
                *(__nv_bfloat162*)&sV0[tid][i] = vhi;
                *(__nv_bfloat162*)&sV1[tid][i] = vlo;
            }
        }
        __syncthreads();

        // S = ah . k^T  (49x128), 3-term split
        float s[16][4];
#pragma unroll
        for (int j = 0; j < 16; j++)
#pragma unroll
            for (int e = 0; e < 4; e++) s[j][e] = 0.f;
#pragma unroll
        for (int kt = 0; kt < 4; kt++) {
            uint32_t a0[4], a1[4];
            uint32_t aro = smem_u32(&sA0[warp * 16 + (lane & 15)][kt * 16 + ((lane >> 4) << 3)]);
            uint32_t aro1 = smem_u32(&sA1[warp * 16 + (lane & 15)][kt * 16 + ((lane >> 4) << 3)]);
            ldsm4(a0[0], a0[1], a0[2], a0[3], aro);
            ldsm4(a1[0], a1[1], a1[2], a1[3], aro1);
#pragma unroll
            for (int p = 0; p < 8; p++) {
                uint32_t bro = (uint32_t)((p * 16 + (lane & 7) + ((lane >> 4) << 3)) * 72
                                          + kt * 16 + (((lane >> 3) & 1) << 3));
                uint32_t bh[4], bl[4];
                ldsm4(bh[0], bh[1], bh[2], bh[3], smem_u32(sK0) + bro * 2);
                ldsm4(bl[0], bl[1], bl[2], bl[3], smem_u32(sK1) + bro * 2);
                mma16816(s[p * 2],     a0, bh[0], bh[1]);
                mma16816(s[p * 2],     a0, bl[0], bl[1]);
                mma16816(s[p * 2],     a1, bh[0], bh[1]);
                mma16816(s[p * 2 + 1], a0, bh[2], bh[3]);
                mma16816(s[p * 2 + 1], a0, bl[2], bl[3]);
                mma16816(s[p * 2 + 1], a1, bh[2], bh[3]);
            }
        }

        // bias1 + mask + online softmax update
#pragma unroll
        for (int rh = 0; rh < 2; rh++) {
            int a = warp * 16 + (lane >> 2) + rh * 8;
            bool av = (a < AG);
            const float* b1p = g_bias1 + (size_t)(h * AG + (av ? a : 0)) * NTOK;
            float mx = m_run[rh];
#pragma unroll
            for (int j = 0; j < 16; j++) {
                int n = n0 + j * 8 + (lane & 3) * 2;
                bool nv = av && (n < NTOK);
                float2 bb = nv ? *(const float2*)(b1p + n) : make_float2(0.f, 0.f);
                float v0 = nv ? (s[j][rh * 2] + bb.x) : -1e30f;
                float v1 = nv ? (s[j][rh * 2 + 1] + bb.y) : -1e30f;
                s[j][rh * 2] = v0;
                s[j][rh * 2 + 1] = v1;
                mx = fmaxf(mx, fmaxf(v0, v1));
            }
            mx = fmaxf(mx, __shfl_xor_sync(0xffffffffu, mx, 1));
            mx = fmaxf(mx, __shfl_xor_sync(0xffffffffu, mx, 2));
            float scale = __expf(m_run[rh] - mx);
            float sum = 0.f;
#pragma unroll
            for (int j = 0; j < 16; j++) {
                float e0 = __expf(s[j][rh * 2] - mx);
                float e1 = __expf(s[j][rh * 2 + 1] - mx);
                s[j][rh * 2] = e0;
                s[j][rh * 2 + 1] = e1;
                sum += e0 + e1;
            }
            sum += __shfl_xor_sync(0xffffffffu, sum, 1);
            sum += __shfl_xor_sync(0xffffffffu, sum, 2);
            l_run[rh] = l_run[rh] * scale + sum;
            m_run[rh] = mx;
#pragma unroll
            for (int j = 0; j < 8; j++) {
                o[j][rh * 2] *= scale;
                o[j][rh * 2 + 1] *= scale;
            }
        }

        // O += P @ V (contraction over 128 n), P from regs, split
#pragma unroll
        for (int kt = 0; kt < 8; kt++) {
            uint32_t ah4[4], al4[4];
#pragma unroll
            for (int q = 0; q < 2; q++) {
                int j = kt * 2 + q;
#pragma unroll
                for (int rh = 0; rh < 2; rh++) {
                    __nv_bfloat16 h0, l0, h1, l1;
                    split2(s[j][rh * 2], h0, l0);
                    split2(s[j][rh * 2 + 1], h1, l1);
                    ah4[q * 2 + rh] = pack_bf2(h0, h1);
                    al4[q * 2 + rh] = pack_bf2(l0, l1);
                }
            }
#pragma unroll
            for (int dp = 0; dp < 4; dp++) {
                uint32_t bro = (uint32_t)((kt * 16 + (lane & 15)) * 72 + dp * 16 + ((lane >> 4) << 3));
                uint32_t vh[4], vl[4];
                ldsm4t(vh[0], vh[1], vh[2], vh[3], smem_u32(sV0) + bro * 2);
                ldsm4t(vl[0], vl[1], vl[2], vl[3], smem_u32(sV1) + bro * 2);
                mma16816(o[dp * 2],     ah4, vh[0], vh[1]);
                mma16816(o[dp * 2],     ah4, vl[0], vl[1]);
                mma16816(o[dp * 2],     al4, vh[0], vh[1]);
                mma16816(o[dp * 2 + 1], ah4, vh[2], vh[3]);
                mma16816(o[dp * 2 + 1], ah4, vl[2], vl[3]);
                mma16816(o[dp * 2 + 1], al4, vh[2], vh[3]);
            }
        }
    }

    // normalize + store
#pragma unroll
    for (int rh = 0; rh < 2; rh++) {
        int a = warp * 16 + (lane >> 2) + rh * 8;
        if (a < AG) {
            float invl = 1.0f / l_run[rh];
            float* dst = g_agentv + ((size_t)bh * AG + a) * HD;
#pragma unroll
            for (int j = 0; j < 8; j++) {
                int d = j * 8 + (lane & 3) * 2;
                *(float2*)(dst + d) = make_float2(o[j][rh * 2] * invl, o[j][rh * 2 + 1] * invl);
            }
        }
    }
}

// ---------------- q-side fused flash (mma.sync) -------------------------------
__global__ void __launch_bounds__(128) qside_mma() {
    __shared__ __nv_bfloat16 sQ[128][72];
    __shared__ __nv_bfloat16 sB0[64][72];
    __shared__ __nv_bfloat16 sB1[64][72];
    int b = blockIdx.z, h = blockIdx.y, m0 = blockIdx.x * 128;
    int tid = threadIdx.x, lane = tid & 31, warp = tid >> 5;

    {
        int row = tid >> 1, c0 = (tid & 1) * 32;
        const float* src = g_agent + (size_t)(b * AG + row) * CH + h * HD + c0;
#pragma unroll
        for (int i = 0; i < 32; i += 2) {
            float2 v = (row < AG) ? *(const float2*)(src + i) : make_float2(0.f, 0.f);
            v.x *= 0.125f; v.y *= 0.125f;
            __nv_bfloat162 hi, lo;
            split2(v.x, hi.x, lo.x);
            split2(v.y, hi.y, lo.y);
            *(__nv_bfloat162*)&sB0[row][c0 + i] = hi;
            *(__nv_bfloat162*)&sB1[row][c0 + i] = lo;
        }
    }

    float acc[2][8][4];
#pragma unroll
    for (int mf = 0; mf < 2; mf++)
#pragma unroll
        for (int j = 0; j < 8; j++)
#pragma unroll
            for (int e = 0; e < 4; e++) acc[mf][j][e] = 0.f;

    for (int term = 0; term < 3; term++) {
        if (term != 1) {
            __syncthreads();
            int row = tid;
            int m = m0 + row;
            const float* src = g_q + ((size_t)b * NTOK + m) * CH + h * HD;
#pragma unroll
            for (int i = 0; i < 64; i += 2) {
                float2 v = (m < NTOK) ? *(const float2*)(src + i) : make_float2(0.f, 0.f);
                __nv_bfloat162 hi;
                hi.x = __float2bfloat16(v.x);
                hi.y = __float2bfloat16(v.y);
                if (term == 0) *(__nv_bfloat162*)&sQ[row][i] = hi;
                else {
                    __nv_bfloat162 lo;
                    lo.x = __float2bfloat16(v.x - __bfloat162float(hi.x));
                    lo.y = __float2bfloat16(v.y - __bfloat162float(hi.y));
                    *(__nv_bfloat162*)&sQ[row][i] = lo;
                }
            }
        }
        __syncthreads();
        __nv_bfloat16 (*Bs)[72] = (term == 1) ? sB1 : sB0;
#pragma unroll
        for (int kt = 0; kt < 4; kt++) {
            uint32_t af[2][4];
#pragma unroll
            for (int mf = 0; mf < 2; mf++)
                ldsm4(af[mf][0], af[mf][1], af[mf][2], af[mf][3],
                      smem_u32(&sQ[warp * 32 + mf * 16 + (lane & 15)][kt * 16 + ((lane >> 4) << 3)]));
#pragma unroll
            for (int p = 0; p < 4; p++) {
                uint32_t br[4];
                ldsm4(br[0], br[1], br[2], br[3],
                      smem_u32(&Bs[p * 16 + (lane & 7) + ((lane >> 4) << 3)][kt * 16 + (((lane >> 3) & 1) << 3)]));
#pragma unroll
                for (int mf = 0; mf < 2; mf++) {
                    mma16816(acc[mf][p * 2],     af[mf], br[0], br[1]);
                    mma16816(acc[mf][p * 2 + 1], af[mf], br[2], br[3]);
                }
            }
        }
    }
    __syncthreads();

    {
        int row = tid >> 1, c0 = (tid & 1) * 32;
        const float* src = g_agentv + ((size_t)(b * NH + h) * AG + row) * HD + c0;
#pragma unroll
        for (int i = 0; i < 32; i += 2) {
            float2 v = (row < AG) ? *(const float2*)(src + i) : make_float2(0.f, 0.f);
            __nv_bfloat162 hi, lo;
            split2(v.x, hi.x, lo.x);
            split2(v.y, hi.y, lo.y);
            *(__nv_bfloat162*)&sB0[row][c0 + i] = hi;
            *(__nv_bfloat162*)&sB1[row][c0 + i] = lo;
        }
    }

    float inv[2][2];
#pragma unroll
    for (int mf = 0; mf < 2; mf++) {
#pragma unroll
        for (int rh = 0; rh < 2; rh++) {
            int m = m0 + warp * 32 + mf * 16 + (lane >> 2) + rh * 8;
            const float* b2 = g_bias2 + ((size_t)h * NTOK + (m < NTOK ? m : 0)) * AG;
            float mx = -1e30f;
#pragma unroll
            for (int j = 0; j < 8; j++)
#pragma unroll
                for (int e = 0; e < 2; e++) {
                    int a = j * 8 + (lane & 3) * 2 + e;
                    float v;
                    if (a < AG) v = acc[mf][j][rh * 2 + e] + ((m < NTOK) ? b2[a] : 0.f);
                    else v = -1e30f;
                    acc[mf][j][rh * 2 + e] = v;
                    mx = fmaxf(mx, v);
                }
            mx = fmaxf(mx, __shfl_xor_sync(0xffffffffu, mx, 1));
            mx = fmaxf(mx, __shfl_xor_sync(0xffffffffu, mx, 2));
            float s = 0.f;
#pragma unroll
            for (int j = 0; j < 8; j++)
#pragma unroll
                for (int e = 0; e < 2; e++) {
                    float ev = __expf(acc[mf][j][rh * 2 + e] - mx);
                    acc[mf][j][rh * 2 + e] = ev;
                    s += ev;
                }
            s += __shfl_xor_sync(0xffffffffu, s, 1);
            s += __shfl_xor_sync(0xffffffffu, s, 2);
            inv[mf][rh] = 1.0f / s;
        }
    }
    __syncthreads();

    float o[2][8][4];
#pragma unroll
    for (int mf = 0; mf < 2; mf++)
#pragma unroll
        for (int j = 0; j < 8; j++)
#pragma unroll
            for (int e = 0; e < 4; e++) o[mf][j][e] = 0.f;

#pragma unroll
    for (int kt = 0; kt < 4; kt++) {
        uint32_t ah_[2][4], al_[2][4];
#pragma unroll
        for (int mf = 0; mf < 2; mf++)
#pragma unroll
            for (int q = 0; q < 2; q++) {
                int j = kt * 2 + q;
#pragma unroll
                for (int rh = 0; rh < 2; rh++) {
                    float v0 = acc[mf][j][rh * 2 + 0] * inv[mf][rh];
                    float v1 = acc[mf][j][rh * 2 + 1] * inv[mf][rh];
                    __nv_bfloat16 h0, l0, h1, l1;
                    split2(v0, h0, l0);
                    split2(v1, h1, l1);
                    ah_[mf][q * 2 + rh] = pack_bf2(h0, h1);
                    al_[mf][q * 2 + rh] = pack_bf2(l0, l1);
                }
            }
#pragma unroll
        for (int dp = 0; dp < 4; dp++) {
            uint32_t bh_[4], bl_[4];
            uint32_t brow = kt * 16 + (lane & 15);
            uint32_t bcol = dp * 16 + ((lane >> 4) << 3);
            ldsm4t(bh_[0], bh_[1], bh_[2], bh_[3], smem_u32(&sB0[brow][bcol]));
            ldsm4t(bl_[0], bl_[1], bl_[2], bl_[3], smem_u32(&sB1[brow][bcol]));
#pragma unroll
            for (int mf = 0; mf < 2; mf++) {
                mma16816(o[mf][dp * 2], ah_[mf], bh_[0], bh_[1]);
                mma16816(o[mf][dp * 2], ah_[mf], bl_[0], bl_[1]);
                mma16816(o[mf][dp * 2], al_[mf], bh_[0], bh_[1]);
                mma16816(o[mf][dp * 2 + 1], ah_[mf], bh_[2], bh_[3]);
                mma16816(o[mf][dp * 2 + 1], ah_[mf], bl_[2], bl_[3]);
                mma16816(o[mf][dp * 2 + 1], al_[mf], bh_[2], bh_[3]);
            }
        }
    }

#pragma unroll
    for (int mf = 0; mf < 2; mf++) {
#pragma unroll
        for (int j = 0; j < 8; j++) {
            int m = m0 + warp * 32 + mf * 16 + (lane >> 2);
            int d = j * 8 + (lane & 3) * 2;
            float* dst = g_pre + ((size_t)b * NTOK + m) * CH + h * HD + d;
            if (m < NTOK)
                *(float2*)dst = make_float2(o[mf][j][0], o[mf][j][1]);
            if (m + 8 < NTOK)
                *(float2*)(dst + 8 * CH) = make_float2(o[mf][j][2], o[mf][j][3]);
        }
    }
}

// ---------------- launch ------------------------------------------------------
extern "C" void kernel_launch(void* const* d_in, const int* in_sizes, int n_in,
                              void* d_out, int out_size) {
    int off = (in_sizes[1] == 1) ? 3 : 1;
    const float* x      = (const float*)d_in[0];
    const float* q_w    = (const float*)d_in[off + 0];
    const float* kv_w   = (const float*)d_in[off + 1];
    const float* proj_w = (const float*)d_in[off + 2];
    const float* proj_b = (const float*)d_in[off + 3];
    const float* dwc_w  = (const float*)d_in[off + 4];
    const float* dwc_b  = (const float*)d_in[off + 5];
    const float* an_b   = (const float*)d_in[off + 6];
    const float* na_b   = (const float*)d_in[off + 7];
    const float* ah_b   = (const float*)d_in[off + 8];
    const float* aw_b   = (const float*)d_in[off + 9];
    const float* ha_b   = (const float*)d_in[off + 10];
    const float* wa_b   = (const float*)d_in[off + 11];
    float* out = (float*)d_out;

    cudaFuncSetAttribute(gemm_split, cudaFuncAttributeMaxDynamicSharedMemorySize, GS_DYN);
    cudaFuncSetAttribute(agent_fused, cudaFuncAttributeMaxDynamicSharedMemorySize, AF_DYN);

    make_bias1<<<dim3(AG, NH), 256>>>(an_b, ah_b, aw_b);
    make_bias2<<<dim3(NTOK, NH), 64>>>(na_b, ha_b, wa_b);

    pack_a<<<MROWS, 256>>>(x);
    pack_b<<<3 * CH, 256>>>(q_w, kv_w, 1);
    gemm_split<<<dim3(1536 / 128, MROWS / 128), 256, GS_DYN>>>(0, nullptr, nullptr);

    agent_pool<<<dim3(AG, BQ), CH>>>();
    agent_fused<<<dim3(NH, BQ), 128, AF_DYN>>>();
    qside_mma<<<dim3(25, NH, BQ), 128>>>();

    pack_a_dwc<<<MROWS, 256>>>(dwc_w, dwc_b);
    pack_b<<<CH, 256>>>(proj_w, nullptr, 0);
    gemm_split<<<dim3(CH / 128, MROWS / 128), 256, GS_DYN>>>(1, proj_b, out);
}